// round 2
// baseline (speedup 1.0000x reference)
#include <cuda_runtime.h>

#define NN 100000
#define NE 1600000
#define INF 128
#define HID 128
#define OF 64

// Scratch (device globals: no allocation allowed)
__device__ float g_agg1[NN * HID];   // sum aggregation of x
__device__ float g_h[NN * HID];      // layer-1 output (post BN+ReLU)
__device__ float g_p[NN * OF];       // h @ W2_l.T
__device__ float g_agg2[NN * OF];    // sum aggregation of p
__device__ int   g_deg[NN];
__device__ float g_invdeg[NN];
__device__ int   g_is64;

// ---------------------------------------------------------------------------
// Detect whether edge_index is int64 or int32. If int64 (little-endian), the
// odd int32 words of the first 256 entries are the high words of values in
// [0, 100000) -> all zero. If int32, they are random edge ids (P(all zero)~0).
// ---------------------------------------------------------------------------
__global__ void detect_kernel(const int* ei32) {
    __shared__ int cnt;
    if (threadIdx.x == 0) cnt = 0;
    __syncthreads();
    if (ei32[2 * threadIdx.x + 1] != 0) atomicAdd(&cnt, 1);
    __syncthreads();
    if (threadIdx.x == 0) g_is64 = (cnt == 0) ? 1 : 0;
}

__global__ void invdeg_kernel() {
    int n = blockIdx.x * blockDim.x + threadIdx.x;
    if (n < NN) g_invdeg[n] = 1.0f / fmaxf((float)g_deg[n], 1.0f);
}

// ---------------------------------------------------------------------------
// Edge pass 1: degree count + sum-aggregate x (128 f32) into g_agg1.
// One warp per edge; lane owns a float4 chunk; vector red.global.add.v4.f32.
// ---------------------------------------------------------------------------
__global__ void edge1_kernel(const void* ei, const float* x) {
    int gt = blockIdx.x * blockDim.x + threadIdx.x;
    int warp = gt >> 5;
    int lane = gt & 31;
    int nw = (gridDim.x * blockDim.x) >> 5;
    const int is64 = g_is64;
    const float4* x4 = (const float4*)x;
    float4* a4 = (float4*)g_agg1;
    for (int e = warp; e < NE; e += nw) {
        int src = 0, dst = 0;
        if (lane == 0) {
            if (is64) {
                const long long* p = (const long long*)ei;
                src = (int)p[e];
                dst = (int)p[NE + e];
            } else {
                const int* p = (const int*)ei;
                src = p[e];
                dst = p[NE + e];
            }
            atomicAdd(&g_deg[dst], 1);
        }
        src = __shfl_sync(0xffffffffu, src, 0);
        dst = __shfl_sync(0xffffffffu, dst, 0);
        float4 v = x4[src * 32 + lane];
        float4* d = a4 + dst * 32 + lane;
        asm volatile("red.global.add.v4.f32 [%0], {%1,%2,%3,%4};"
                     :: "l"(d), "f"(v.x), "f"(v.y), "f"(v.z), "f"(v.w)
                     : "memory");
    }
}

// ---------------------------------------------------------------------------
// Edge pass 2: sum-aggregate p (64 f32) into g_agg2. Two edges per warp
// (16 lanes x float4 each).
// ---------------------------------------------------------------------------
__global__ void edge2_kernel(const void* ei) {
    int gt = blockIdx.x * blockDim.x + threadIdx.x;
    int warp = gt >> 5;
    int lane = gt & 31;
    int nw = (gridDim.x * blockDim.x) >> 5;
    int half = lane >> 4;
    int sub = lane & 15;
    const int is64 = g_is64;
    const float4* p4 = (const float4*)g_p;
    float4* a4 = (float4*)g_agg2;
    for (int eb = warp; eb < NE / 2; eb += nw) {
        int e = 2 * eb + half;
        int src = 0, dst = 0;
        if (sub == 0) {
            if (is64) {
                const long long* p = (const long long*)ei;
                src = (int)p[e];
                dst = (int)p[NE + e];
            } else {
                const int* p = (const int*)ei;
                src = p[e];
                dst = p[NE + e];
            }
        }
        src = __shfl_sync(0xffffffffu, src, half << 4);
        dst = __shfl_sync(0xffffffffu, dst, half << 4);
        float4 v = p4[src * 16 + sub];
        float4* d = a4 + dst * 16 + sub;
        asm volatile("red.global.add.v4.f32 [%0], {%1,%2,%3,%4};"
                     :: "l"(d), "f"(v.x), "f"(v.y), "f"(v.z), "f"(v.w)
                     : "memory");
    }
}

// ---------------------------------------------------------------------------
// Fused layer-1 GEMM: h = relu(BN( (agg1*invdeg) @ W1_l.T + b1 + x @ W1_r.T ))
// 128-node x 128-feat tile per block, 256 threads, 8x8 micro-tile per thread.
// W is stored TRANSPOSED in smem: Ws[k*WS1 + f] = W[f][k], padded stride 132
// so the float4 b-loads stay 16B-aligned. Transpose store pattern is
// conflict-free (warp spans 32 distinct f for fixed k).
// A staged in 32-k chunks (stride-129: conflict-free staging stores,
// 2-address broadcast compute reads).
// ---------------------------------------------------------------------------
#define WS1 132
__global__ void __launch_bounds__(256, 2) gemm1_kernel(
    const float* x, const float* W1l, const float* W1r,
    const float* b1, const float* gmm, const float* bet,
    const float* mean, const float* var)
{
    extern __shared__ float sm[];
    float* Ws = sm;                  // 128 rows (k) x 132 (f padded)
    float* As = sm + HID * WS1;      // 32*129
    const int tid = threadIdx.x;
    const int n0 = blockIdx.x * 128;
    const int r = tid >> 4, cg = tid & 15;
    const int rn = r * 8, fb = cg * 8;

    float acc[8][8];
#pragma unroll
    for (int i = 0; i < 8; i++)
#pragma unroll
        for (int j = 0; j < 8; j++) acc[i][j] = 0.f;

    for (int pass = 0; pass < 2; pass++) {
        const float* A = pass ? x : g_agg1;
        const float* W = pass ? W1r : W1l;
        __syncthreads();  // previous pass compute done before Ws overwrite
        {
            // transpose load: Ws[k*WS1 + f] = W[f*INF + k]
            const float4* W4 = (const float4*)W;
#pragma unroll
            for (int it = 0; it < 16; it++) {
                int i = tid + it * 256;          // chunk index, 4096 total
                int f = i & 127;                 // warp: 32 distinct f
                int kq = i >> 7;                 // k block of 4
                float4 w = W4[f * 32 + kq];
                int kb = kq * 4;
                Ws[(kb + 0) * WS1 + f] = w.x;
                Ws[(kb + 1) * WS1 + f] = w.y;
                Ws[(kb + 2) * WS1 + f] = w.z;
                Ws[(kb + 3) * WS1 + f] = w.w;
            }
        }
        const float4* A4 = (const float4*)A;
        for (int kc = 0; kc < 4; kc++) {
            __syncthreads();
            // stage As[k][node], k in [kc*32, kc*32+32)
            for (int t = tid; t < 1024; t += 256) {
                int node = t >> 3, kq = t & 7;
                int gn = n0 + node;
                float4 v = make_float4(0.f, 0.f, 0.f, 0.f);
                if (gn < NN) {
                    v = A4[gn * 32 + kc * 8 + kq];
                    if (pass == 0) {
                        float s = g_invdeg[gn];
                        v.x *= s; v.y *= s; v.z *= s; v.w *= s;
                    }
                }
                int kb = kq * 4;
                As[(kb + 0) * 129 + node] = v.x;
                As[(kb + 1) * 129 + node] = v.y;
                As[(kb + 2) * 129 + node] = v.z;
                As[(kb + 3) * 129 + node] = v.w;
            }
            __syncthreads();
#pragma unroll
            for (int kk = 0; kk < 32; kk++) {
                float a[8], b[8];
#pragma unroll
                for (int i = 0; i < 8; i++) a[i] = As[kk * 129 + rn + i];
                const float4* wr = (const float4*)(Ws + (kc * 32 + kk) * WS1 + fb);
                float4 b0 = wr[0], b1v = wr[1];
                b[0] = b0.x; b[1] = b0.y; b[2] = b0.z; b[3] = b0.w;
                b[4] = b1v.x; b[5] = b1v.y; b[6] = b1v.z; b[7] = b1v.w;
#pragma unroll
                for (int i = 0; i < 8; i++)
#pragma unroll
                    for (int j = 0; j < 8; j++)
                        acc[i][j] = fmaf(a[i], b[j], acc[i][j]);
            }
        }
    }

    // epilogue: +b1, BN(eval), ReLU
    float sc[8], sh[8], bb[8];
#pragma unroll
    for (int j = 0; j < 8; j++) {
        int f = fb + j;
        float s = rsqrtf(var[f] + 1e-5f) * gmm[f];
        sc[j] = s;
        sh[j] = bet[f] - mean[f] * s;
        bb[j] = b1[f];
    }
#pragma unroll
    for (int i = 0; i < 8; i++) {
        int n = n0 + rn + i;
        if (n < NN) {
            float o[8];
#pragma unroll
            for (int j = 0; j < 8; j++) {
                float v = (acc[i][j] + bb[j]) * sc[j] + sh[j];
                o[j] = fmaxf(v, 0.f);
            }
            float4* dst = (float4*)(g_h + n * HID + fb);
            dst[0] = make_float4(o[0], o[1], o[2], o[3]);
            dst[1] = make_float4(o[4], o[5], o[6], o[7]);
        }
    }
}

// ---------------------------------------------------------------------------
// Layer-2 GEMMs (OUT=64, K=128): EPI=0 -> g_p = h @ W.T
//                                EPI=1 -> C  = h @ W.T + agg2*invdeg + b2
// Ws transposed: Ws[k*WS2 + f] = W[f][k], stride 68.
// ---------------------------------------------------------------------------
#define WS2 68
template <int EPI>
__global__ void __launch_bounds__(256, 2) gemm2_kernel(
    const float* W, const float* b2, float* C)
{
    extern __shared__ float sm[];
    float* Ws = sm;                  // 128 rows (k) x 68 (f padded)
    float* As = sm + HID * WS2;      // 32*129
    const int tid = threadIdx.x;
    const int n0 = blockIdx.x * 128;
    const int r = tid >> 4, cg = tid & 15;
    const int rn = r * 8, fb = cg * 4;

    float acc[8][4];
#pragma unroll
    for (int i = 0; i < 8; i++)
#pragma unroll
        for (int j = 0; j < 4; j++) acc[i][j] = 0.f;

    {
        // transpose load: Ws[k*WS2 + f] = W[f*HID + k]; 2048 float4 chunks
        const float4* W4 = (const float4*)W;
#pragma unroll
        for (int it = 0; it < 8; it++) {
            int i = tid + it * 256;
            int f = i & 63;              // warp: 32 distinct f (mod 32 distinct)
            int kq = i >> 6;
            float4 w = W4[f * 32 + kq];
            int kb = kq * 4;
            Ws[(kb + 0) * WS2 + f] = w.x;
            Ws[(kb + 1) * WS2 + f] = w.y;
            Ws[(kb + 2) * WS2 + f] = w.z;
            Ws[(kb + 3) * WS2 + f] = w.w;
        }
    }
    const float4* A4 = (const float4*)g_h;
    for (int kc = 0; kc < 4; kc++) {
        __syncthreads();
        for (int t = tid; t < 1024; t += 256) {
            int node = t >> 3, kq = t & 7;
            int gn = n0 + node;
            float4 v = make_float4(0.f, 0.f, 0.f, 0.f);
            if (gn < NN) v = A4[gn * 32 + kc * 8 + kq];
            int kb = kq * 4;
            As[(kb + 0) * 129 + node] = v.x;
            As[(kb + 1) * 129 + node] = v.y;
            As[(kb + 2) * 129 + node] = v.z;
            As[(kb + 3) * 129 + node] = v.w;
        }
        __syncthreads();
#pragma unroll
        for (int kk = 0; kk < 32; kk++) {
            float a[8];
#pragma unroll
            for (int i = 0; i < 8; i++) a[i] = As[kk * 129 + rn + i];
            float4 b = ((const float4*)(Ws + (kc * 32 + kk) * WS2))[cg];
#pragma unroll
            for (int i = 0; i < 8; i++) {
                acc[i][0] = fmaf(a[i], b.x, acc[i][0]);
                acc[i][1] = fmaf(a[i], b.y, acc[i][1]);
                acc[i][2] = fmaf(a[i], b.z, acc[i][2]);
                acc[i][3] = fmaf(a[i], b.w, acc[i][3]);
            }
        }
    }

#pragma unroll
    for (int i = 0; i < 8; i++) {
        int n = n0 + rn + i;
        if (n < NN) {
            if (EPI == 0) {
                ((float4*)(g_p + n * OF + fb))[0] =
                    make_float4(acc[i][0], acc[i][1], acc[i][2], acc[i][3]);
            } else {
                float4 e = ((const float4*)(g_agg2 + n * OF + fb))[0];
                float id = g_invdeg[n];
                float4 bb = ((const float4*)b2)[cg];
                float4 o;
                o.x = acc[i][0] + e.x * id + bb.x;
                o.y = acc[i][1] + e.y * id + bb.y;
                o.z = acc[i][2] + e.z * id + bb.z;
                o.w = acc[i][3] + e.w * id + bb.w;
                ((float4*)(C + n * OF + fb))[0] = o;
            }
        }
    }
}

// ---------------------------------------------------------------------------
// Launch
// ---------------------------------------------------------------------------
extern "C" void kernel_launch(void* const* d_in, const int* in_sizes, int n_in,
                              void* d_out, int out_size) {
    const float* x     = (const float*)d_in[0];
    const void*  ei    = d_in[1];
    const float* W1l   = (const float*)d_in[2];
    const float* b1    = (const float*)d_in[3];
    const float* W1r   = (const float*)d_in[4];
    const float* gmm   = (const float*)d_in[5];
    const float* bet   = (const float*)d_in[6];
    const float* mean  = (const float*)d_in[7];
    const float* var   = (const float*)d_in[8];
    const float* W2l   = (const float*)d_in[9];
    const float* b2    = (const float*)d_in[10];
    const float* W2r   = (const float*)d_in[11];
    float* out = (float*)d_out;

    const int SM1 = (HID * WS1 + 32 * 129) * 4;
    const int SM2 = (HID * WS2 + 32 * 129) * 4;
    cudaFuncSetAttribute(gemm1_kernel, cudaFuncAttributeMaxDynamicSharedMemorySize, SM1);
    cudaFuncSetAttribute(gemm2_kernel<0>, cudaFuncAttributeMaxDynamicSharedMemorySize, SM2);
    cudaFuncSetAttribute(gemm2_kernel<1>, cudaFuncAttributeMaxDynamicSharedMemorySize, SM2);

    void *agg1p = 0, *agg2p = 0, *degp = 0;
    cudaGetSymbolAddress(&agg1p, g_agg1);
    cudaGetSymbolAddress(&agg2p, g_agg2);
    cudaGetSymbolAddress(&degp, g_deg);

    detect_kernel<<<1, 256>>>((const int*)ei);
    cudaMemsetAsync(agg1p, 0, sizeof(float) * NN * HID, 0);
    cudaMemsetAsync(agg2p, 0, sizeof(float) * NN * OF, 0);
    cudaMemsetAsync(degp, 0, sizeof(int) * NN, 0);

    edge1_kernel<<<2048, 256>>>(ei, x);
    invdeg_kernel<<<(NN + 255) / 256, 256>>>();

    const int NB = (NN + 127) / 128;  // 782
    gemm1_kernel<<<NB, 256, SM1>>>(x, W1l, W1r, b1, gmm, bet, mean, var);
    gemm2_kernel<0><<<NB, 256, SM2>>>(W2l, b2, nullptr);
    edge2_kernel<<<2048, 256>>>(ei);
    gemm2_kernel<1><<<NB, 256, SM2>>>(W2r, b2, out);
}

// round 3
// speedup vs baseline: 1.1778x; 1.1778x over previous
#include <cuda_runtime.h>
#include <mma.h>
using namespace nvcuda;

#define NN 100000
#define NNP 100096           // padded to 782*128
#define NE 1600000
#define HID 128
#define OF 64

// Scratch (device globals: no allocation allowed)
__device__ float g_agg1[NNP * HID];  // sum aggregation of x (padded, memset 0)
__device__ float g_h[NNP * HID];     // layer-1 output (post BN+ReLU)
__device__ float g_p[NNP * OF];      // h @ W2_l.T
__device__ float g_q[NNP * OF];      // h @ W2_r.T
__device__ float g_agg2[NN * OF];    // sum aggregation of p
__device__ int   g_deg[NNP];
__device__ float g_invdeg[NNP];
__device__ int   g_is64;

__device__ __forceinline__ float f2tf(float v) {
    unsigned u;
    asm("cvt.rna.tf32.f32 %0, %1;" : "=r"(u) : "f"(v));
    return __uint_as_float(u);
}

// ---------------------------------------------------------------------------
// int64-vs-int32 edge index detection (hi words of first 256 entries all zero
// <=> int64, since node ids < 100000).
// ---------------------------------------------------------------------------
__global__ void detect_kernel(const int* ei32) {
    __shared__ int cnt;
    if (threadIdx.x == 0) cnt = 0;
    __syncthreads();
    if (ei32[2 * threadIdx.x + 1] != 0) atomicAdd(&cnt, 1);
    __syncthreads();
    if (threadIdx.x == 0) g_is64 = (cnt == 0) ? 1 : 0;
}

__global__ void invdeg_kernel() {
    int n = blockIdx.x * blockDim.x + threadIdx.x;
    if (n < NNP) g_invdeg[n] = 1.0f / fmaxf((float)g_deg[n], 1.0f);
}

// ---------------------------------------------------------------------------
// Edge pass 1: degree count + sum-aggregate x (128 f32) into g_agg1.
// One warp per edge; lane owns a float4; vector red.global.add.v4.f32.
// ---------------------------------------------------------------------------
__global__ void edge1_kernel(const void* ei, const float* x) {
    int gt = blockIdx.x * blockDim.x + threadIdx.x;
    int warp = gt >> 5;
    int lane = gt & 31;
    int nw = (gridDim.x * blockDim.x) >> 5;
    const int is64 = g_is64;
    const float4* x4 = (const float4*)x;
    float4* a4 = (float4*)g_agg1;
    for (int e = warp; e < NE; e += nw) {
        int src = 0, dst = 0;
        if (lane == 0) {
            if (is64) {
                const long long* p = (const long long*)ei;
                src = (int)p[e];
                dst = (int)p[NE + e];
            } else {
                const int* p = (const int*)ei;
                src = p[e];
                dst = p[NE + e];
            }
            atomicAdd(&g_deg[dst], 1);
        }
        src = __shfl_sync(0xffffffffu, src, 0);
        dst = __shfl_sync(0xffffffffu, dst, 0);
        float4 v = x4[src * 32 + lane];
        float4* d = a4 + dst * 32 + lane;
        asm volatile("red.global.add.v4.f32 [%0], {%1,%2,%3,%4};"
                     :: "l"(d), "f"(v.x), "f"(v.y), "f"(v.z), "f"(v.w)
                     : "memory");
    }
}

// ---------------------------------------------------------------------------
// Edge pass 2: sum-aggregate p (64 f32) into g_agg2. Two edges per warp.
// ---------------------------------------------------------------------------
__global__ void edge2_kernel(const void* ei) {
    int gt = blockIdx.x * blockDim.x + threadIdx.x;
    int warp = gt >> 5;
    int lane = gt & 31;
    int nw = (gridDim.x * blockDim.x) >> 5;
    int half = lane >> 4;
    int sub = lane & 15;
    const int is64 = g_is64;
    const float4* p4 = (const float4*)g_p;
    float4* a4 = (float4*)g_agg2;
    for (int eb = warp; eb < NE / 2; eb += nw) {
        int e = 2 * eb + half;
        int src = 0, dst = 0;
        if (sub == 0) {
            if (is64) {
                const long long* p = (const long long*)ei;
                src = (int)p[e];
                dst = (int)p[NE + e];
            } else {
                const int* p = (const int*)ei;
                src = p[e];
                dst = p[NE + e];
            }
        }
        src = __shfl_sync(0xffffffffu, src, half << 4);
        dst = __shfl_sync(0xffffffffu, dst, half << 4);
        float4 v = p4[src * 16 + sub];
        float4* d = a4 + dst * 16 + sub;
        asm volatile("red.global.add.v4.f32 [%0], {%1,%2,%3,%4};"
                     :: "l"(d), "f"(v.x), "f"(v.y), "f"(v.z), "f"(v.w)
                     : "memory");
    }
}

// ---------------------------------------------------------------------------
// Layer-1 GEMM on tensor cores (tf32 wmma, K=256 concat):
//   h = relu(BN( [agg1*invdeg | x] @ [W1l ; W1r].T + b1 ))
// CTA: 128 nodes x 128 feats, 8 warps as 4(m) x 2(n); warp tile 32x64.
// smem union: staging { As[128][36], Ws[32][132] }  vs  Cs[128][136].
// ---------------------------------------------------------------------------
#define ALD 36
#define WLD 132
#define CLD 136
#define SM1_FLOATS (128 * CLD + 256)   // Cs + S/T tables

__global__ void __launch_bounds__(256, 2) gemm1_kernel(
    const float* __restrict__ x,
    const float* __restrict__ W1l, const float* __restrict__ W1r,
    const float* __restrict__ b1, const float* __restrict__ gmm,
    const float* __restrict__ bet, const float* __restrict__ mean,
    const float* __restrict__ var)
{
    extern __shared__ float sm[];
    float* As = sm;                         // 128 x 36
    float* Ws = sm + 128 * ALD;             // 32 x 132
    float* Cs = sm;                         // 128 x 136 (union)
    float* Ssc = sm + 128 * CLD;            // 128
    float* Ssh = Ssc + 128;                 // 128

    const int tid = threadIdx.x;
    const int wid = tid >> 5;
    const int wm = wid >> 1;   // 0..3 -> rows wm*32
    const int wn = wid & 1;    // 0..1 -> cols wn*64
    const int n0 = blockIdx.x * 128;

    // BN fold: out = v*S + T, S = gamma*rsqrt(var+eps), T = (b1-mean)*S + beta
    if (tid < 128) {
        float s = rsqrtf(var[tid] + 1e-5f) * gmm[tid];
        Ssc[tid] = s;
        Ssh[tid] = (b1[tid] - mean[tid]) * s + bet[tid];
    }

    wmma::fragment<wmma::accumulator, 16, 16, 8, float> acc[2][4];
#pragma unroll
    for (int i = 0; i < 2; i++)
#pragma unroll
        for (int j = 0; j < 4; j++) wmma::fill_fragment(acc[i][j], 0.f);

    const float4* X4 = (const float4*)x;
    const float4* A14 = (const float4*)g_agg1;

    for (int kc = 0; kc < 8; kc++) {
        const int isagg = (kc < 4);
        const int kq0 = (kc & 3) * 8;       // float4 offset within row
        __syncthreads();
        // stage As (128 rows x 32 k), converted to tf32
        for (int t = tid; t < 1024; t += 256) {
            int row = t >> 3, q = t & 7;
            int gn = n0 + row;
            float4 v;
            if (isagg) {
                v = A14[(size_t)gn * 32 + kq0 + q];
                float s = g_invdeg[gn];
                v.x *= s; v.y *= s; v.z *= s; v.w *= s;
            } else {
                v = make_float4(0.f, 0.f, 0.f, 0.f);
                if (gn < NN) v = X4[(size_t)gn * 32 + kq0 + q];
            }
            float4 c = make_float4(f2tf(v.x), f2tf(v.y), f2tf(v.z), f2tf(v.w));
            *(float4*)(As + row * ALD + q * 4) = c;
        }
        // stage Ws transposed: Ws[k][f] = W[f][k]
        const float4* W4 = (const float4*)(isagg ? W1l : W1r);
        for (int t = tid; t < 1024; t += 256) {
            int f = t & 127, q = t >> 7;
            float4 w = W4[f * 32 + kq0 + q];
            int kb = q * 4;
            Ws[(kb + 0) * WLD + f] = f2tf(w.x);
            Ws[(kb + 1) * WLD + f] = f2tf(w.y);
            Ws[(kb + 2) * WLD + f] = f2tf(w.z);
            Ws[(kb + 3) * WLD + f] = f2tf(w.w);
        }
        __syncthreads();
#pragma unroll
        for (int k8 = 0; k8 < 4; k8++) {
            wmma::fragment<wmma::matrix_a, 16, 16, 8, wmma::precision::tf32,
                           wmma::row_major> a[2];
#pragma unroll
            for (int i = 0; i < 2; i++)
                wmma::load_matrix_sync(a[i], As + (wm * 32 + i * 16) * ALD + k8 * 8, ALD);
#pragma unroll
            for (int nf = 0; nf < 4; nf++) {
                wmma::fragment<wmma::matrix_b, 16, 16, 8, wmma::precision::tf32,
                               wmma::row_major> b;
                wmma::load_matrix_sync(b, Ws + (k8 * 8) * WLD + wn * 64 + nf * 16, WLD);
#pragma unroll
                for (int i = 0; i < 2; i++)
                    wmma::mma_sync(acc[i][nf], a[i], b, acc[i][nf]);
            }
        }
    }

    __syncthreads();   // staging dead; Cs takes over the union
#pragma unroll
    for (int i = 0; i < 2; i++)
#pragma unroll
        for (int nf = 0; nf < 4; nf++)
            wmma::store_matrix_sync(Cs + (wm * 32 + i * 16) * CLD + wn * 64 + nf * 16,
                                    acc[i][nf], CLD, wmma::mem_row_major);
    __syncthreads();

    // epilogue: BN + ReLU, write g_h (padded -> unconditional stores)
    {
        int row = tid >> 1, half = tid & 1;
        int gn = n0 + row;
        float* dst = g_h + (size_t)gn * HID + half * 64;
        const float* src = Cs + row * CLD + half * 64;
#pragma unroll
        for (int j4 = 0; j4 < 16; j4++) {
            float4 v = *(const float4*)(src + j4 * 4);
            int f = half * 64 + j4 * 4;
            float4 o;
            o.x = fmaxf(v.x * Ssc[f + 0] + Ssh[f + 0], 0.f);
            o.y = fmaxf(v.y * Ssc[f + 1] + Ssh[f + 1], 0.f);
            o.z = fmaxf(v.z * Ssc[f + 2] + Ssh[f + 2], 0.f);
            o.w = fmaxf(v.w * Ssc[f + 3] + Ssh[f + 3], 0.f);
            *(float4*)(dst + j4 * 4) = o;
        }
    }
}

// ---------------------------------------------------------------------------
// Layer-2 fused GEMM (tf32 wmma): [p | q] = h @ [W2l ; W2r].T   (N-concat)
// Direct fragment stores to padded g_p / g_q.
// ---------------------------------------------------------------------------
#define SM2_FLOATS (128 * ALD + 32 * WLD)

__global__ void __launch_bounds__(256, 2) gemm2_kernel(
    const float* __restrict__ W2l, const float* __restrict__ W2r)
{
    extern __shared__ float sm[];
    float* As = sm;
    float* Ws = sm + 128 * ALD;

    const int tid = threadIdx.x;
    const int wid = tid >> 5;
    const int wm = wid >> 1;
    const int wn = wid & 1;
    const int n0 = blockIdx.x * 128;

    wmma::fragment<wmma::accumulator, 16, 16, 8, float> acc[2][4];
#pragma unroll
    for (int i = 0; i < 2; i++)
#pragma unroll
        for (int j = 0; j < 4; j++) wmma::fill_fragment(acc[i][j], 0.f);

    const float4* H4 = (const float4*)g_h;

    for (int kc = 0; kc < 4; kc++) {
        const int kq0 = kc * 8;
        __syncthreads();
        for (int t = tid; t < 1024; t += 256) {
            int row = t >> 3, q = t & 7;
            float4 v = H4[(size_t)(n0 + row) * 32 + kq0 + q];
            float4 c = make_float4(f2tf(v.x), f2tf(v.y), f2tf(v.z), f2tf(v.w));
            *(float4*)(As + row * ALD + q * 4) = c;
        }
        for (int t = tid; t < 1024; t += 256) {
            int f = t & 127, q = t >> 7;
            const float4* W4 = (f < 64) ? (const float4*)W2l + f * 32
                                        : (const float4*)W2r + (f - 64) * 32;
            float4 w = W4[kq0 + q];
            int kb = q * 4;
            Ws[(kb + 0) * WLD + f] = f2tf(w.x);
            Ws[(kb + 1) * WLD + f] = f2tf(w.y);
            Ws[(kb + 2) * WLD + f] = f2tf(w.z);
            Ws[(kb + 3) * WLD + f] = f2tf(w.w);
        }
        __syncthreads();
#pragma unroll
        for (int k8 = 0; k8 < 4; k8++) {
            wmma::fragment<wmma::matrix_a, 16, 16, 8, wmma::precision::tf32,
                           wmma::row_major> a[2];
#pragma unroll
            for (int i = 0; i < 2; i++)
                wmma::load_matrix_sync(a[i], As + (wm * 32 + i * 16) * ALD + k8 * 8, ALD);
#pragma unroll
            for (int nf = 0; nf < 4; nf++) {
                wmma::fragment<wmma::matrix_b, 16, 16, 8, wmma::precision::tf32,
                               wmma::row_major> b;
                wmma::load_matrix_sync(b, Ws + (k8 * 8) * WLD + wn * 64 + nf * 16, WLD);
#pragma unroll
                for (int i = 0; i < 2; i++)
                    wmma::mma_sync(acc[i][nf], a[i], b, acc[i][nf]);
            }
        }
    }

    // direct stores: wn=0 -> g_p (cols 0..63), wn=1 -> g_q (cols 0..63)
    float* base = wn ? g_q : g_p;
#pragma unroll
    for (int i = 0; i < 2; i++)
#pragma unroll
        for (int nf = 0; nf < 4; nf++)
            wmma::store_matrix_sync(
                base + (size_t)(n0 + wm * 32 + i * 16) * OF + nf * 16,
                acc[i][nf], OF, wmma::mem_row_major);
}

// ---------------------------------------------------------------------------
// Final: out = q + agg2*invdeg + b2   (elementwise, guarded to NN)
// ---------------------------------------------------------------------------
__global__ void final_kernel(const float* __restrict__ b2, float* __restrict__ out) {
    int t = blockIdx.x * blockDim.x + threadIdx.x;
    if (t >= NN * 16) return;
    int n = t >> 4, j = t & 15;
    float4 q = ((const float4*)g_q)[n * 16 + j];
    float4 a = ((const float4*)g_agg2)[n * 16 + j];
    float id = g_invdeg[n];
    float4 bb = ((const float4*)b2)[j];
    float4 o;
    o.x = q.x + a.x * id + bb.x;
    o.y = q.y + a.y * id + bb.y;
    o.z = q.z + a.z * id + bb.z;
    o.w = q.w + a.w * id + bb.w;
    ((float4*)out)[n * 16 + j] = o;
}

// ---------------------------------------------------------------------------
// Launch
// ---------------------------------------------------------------------------
extern "C" void kernel_launch(void* const* d_in, const int* in_sizes, int n_in,
                              void* d_out, int out_size) {
    const float* x    = (const float*)d_in[0];
    const void*  ei   = d_in[1];
    const float* W1l  = (const float*)d_in[2];
    const float* b1   = (const float*)d_in[3];
    const float* W1r  = (const float*)d_in[4];
    const float* gmm  = (const float*)d_in[5];
    const float* bet  = (const float*)d_in[6];
    const float* mean = (const float*)d_in[7];
    const float* var  = (const float*)d_in[8];
    const float* W2l  = (const float*)d_in[9];
    const float* b2   = (const float*)d_in[10];
    const float* W2r  = (const float*)d_in[11];
    float* out = (float*)d_out;

    const int SM1 = SM1_FLOATS * 4;
    const int SM2 = SM2_FLOATS * 4;
    cudaFuncSetAttribute(gemm1_kernel, cudaFuncAttributeMaxDynamicSharedMemorySize, SM1);
    cudaFuncSetAttribute(gemm2_kernel, cudaFuncAttributeMaxDynamicSharedMemorySize, SM2);

    void *agg1p = 0, *agg2p = 0, *degp = 0;
    cudaGetSymbolAddress(&agg1p, g_agg1);
    cudaGetSymbolAddress(&agg2p, g_agg2);
    cudaGetSymbolAddress(&degp, g_deg);

    detect_kernel<<<1, 256>>>((const int*)ei);
    cudaMemsetAsync(agg1p, 0, sizeof(float) * NNP * HID, 0);
    cudaMemsetAsync(agg2p, 0, sizeof(float) * NN * OF, 0);
    cudaMemsetAsync(degp, 0, sizeof(int) * NNP, 0);

    edge1_kernel<<<2048, 256>>>(ei, x);
    invdeg_kernel<<<(NNP + 255) / 256, 256>>>();

    const int NB = NNP / 128;  // 782
    gemm1_kernel<<<NB, 256, SM1>>>(x, W1l, W1r, b1, gmm, bet, mean, var);
    gemm2_kernel<<<NB, 256, SM2>>>(W2l, W2r);
    edge2_kernel<<<2048, 256>>>(ei);
    final_kernel<<<(NN * 16 + 255) / 256, 256>>>(b2, out);
}

// round 4
// speedup vs baseline: 1.8419x; 1.5638x over previous
#include <cuda_runtime.h>
#include <mma.h>
using namespace nvcuda;

#define NN 100000
#define NNP 100096           // 782*128
#define NE 1600000
#define HID 128
#define OF 64

// ---------------- scratch (device globals; no allocation allowed) ----------
__device__ float g_agg1[NNP * HID];  // mean aggregation of x (invdeg folded)
__device__ float g_h[NNP * HID];     // layer-1 output (post BN+ReLU)
__device__ float g_p[NNP * OF];      // h @ W2_l.T
__device__ float g_q[NNP * OF];      // h @ W2_r.T
__device__ float g_agg2[NN * OF];    // mean aggregation of p
__device__ float g_wt1[256 * HID];   // [W1l;W1r] transposed [k][f], tf32
__device__ float g_wt2[HID * HID];   // [W2l|W2r] transposed [k][f], tf32
__device__ int   g_deg[NNP];
__device__ float g_invdeg[NNP];
__device__ int   g_off[NNP + 1];     // CSR offsets (by dst)
__device__ int   g_cur[NNP];         // counting-sort cursors
__device__ int   g_csrc[NE];         // src sorted by dst
__device__ int   g_tmp[NNP];         // block-local inclusive scans
__device__ int   g_bsum[1024];
__device__ int   g_boff[1024];
__device__ int   g_is64;

__device__ __forceinline__ float f2tf(float v) {
    unsigned u;
    asm("cvt.rna.tf32.f32 %0, %1;" : "=r"(u) : "f"(v));
    return __uint_as_float(u);
}

#define CPA16(dst, src) \
    asm volatile("cp.async.cg.shared.global [%0], [%1], 16;" :: "r"(dst), "l"(src))
#define CPA16Z(dst, src, sz) \
    asm volatile("cp.async.cg.shared.global [%0], [%1], 16, %2;" :: "r"(dst), "l"(src), "r"(sz))
#define CPA_COMMIT() asm volatile("cp.async.commit_group;")
#define CPA_WAIT1()  asm volatile("cp.async.wait_group 1;")
#define CPA_WAIT0()  asm volatile("cp.async.wait_group 0;")

// ---------------------------------------------------------------------------
// dtype detection: int64 edge_index <=> hi words of first 256 entries all 0
// ---------------------------------------------------------------------------
__global__ void detect_kernel(const int* ei32) {
    __shared__ int cnt;
    if (threadIdx.x == 0) cnt = 0;
    __syncthreads();
    if (ei32[2 * threadIdx.x + 1] != 0) atomicAdd(&cnt, 1);
    __syncthreads();
    if (threadIdx.x == 0) g_is64 = (cnt == 0) ? 1 : 0;
}

__device__ __forceinline__ int ld_edge(const void* ei, long long idx, int is64) {
    return is64 ? (int)((const long long*)ei)[idx] : ((const int*)ei)[idx];
}

// ---------------------------------------------------------------------------
// degree count (thread per edge, int atomics only)
// ---------------------------------------------------------------------------
__global__ void deg_kernel(const void* ei) {
    int e = blockIdx.x * blockDim.x + threadIdx.x;
    if (e < NE) {
        int dst = ld_edge(ei, (long long)NE + e, g_is64);
        atomicAdd(&g_deg[dst], 1);
    }
}

__global__ void invdeg_kernel() {
    int n = blockIdx.x * blockDim.x + threadIdx.x;
    if (n < NNP) g_invdeg[n] = 1.0f / fmaxf((float)g_deg[n], 1.0f);
}

// ---------------------------------------------------------------------------
// 3-phase exclusive scan of degrees -> g_off, plus cursor copy
// ---------------------------------------------------------------------------
__global__ void scan1_kernel() {
    __shared__ int s[128];
    int i = blockIdx.x * 128 + threadIdx.x;
    int t = threadIdx.x;
    s[t] = g_deg[i];
    __syncthreads();
    for (int o = 1; o < 128; o <<= 1) {
        int v = (t >= o) ? s[t - o] : 0;
        __syncthreads();
        s[t] += v;
        __syncthreads();
    }
    g_tmp[i] = s[t];
    if (t == 127) g_bsum[blockIdx.x] = s[127];
}
__global__ void scan2_kernel(int nb) {
    __shared__ int s[1024];
    int t = threadIdx.x;
    int own = (t < nb) ? g_bsum[t] : 0;
    s[t] = own;
    __syncthreads();
    for (int o = 1; o < 1024; o <<= 1) {
        int v = (t >= o) ? s[t - o] : 0;
        __syncthreads();
        s[t] += v;
        __syncthreads();
    }
    if (t < nb) g_boff[t] = s[t] - own;   // exclusive
}
__global__ void scan3_kernel() {
    int i = blockIdx.x * 128 + threadIdx.x;
    g_off[i + 1] = g_tmp[i] + g_boff[blockIdx.x];
    if (i == 0) g_off[0] = 0;
}
__global__ void cur_kernel() {
    int i = blockIdx.x * blockDim.x + threadIdx.x;
    if (i < NNP) g_cur[i] = g_off[i];
}

// ---------------------------------------------------------------------------
// counting sort: csrc sorted by dst
// ---------------------------------------------------------------------------
__global__ void sort_kernel(const void* ei) {
    int e = blockIdx.x * blockDim.x + threadIdx.x;
    if (e < NE) {
        int is64 = g_is64;
        int src = ld_edge(ei, e, is64);
        int dst = ld_edge(ei, (long long)NE + e, is64);
        int pos = atomicAdd(&g_cur[dst], 1);
        g_csrc[pos] = src;
    }
}

// ---------------------------------------------------------------------------
// CSR mean-aggregate x (128 f) -> g_agg1. Warp per node, no atomics.
// ---------------------------------------------------------------------------
__global__ void agg1_kernel(const float* __restrict__ x) {
    int w = (blockIdx.x * blockDim.x + threadIdx.x) >> 5;
    int lane = threadIdx.x & 31;
    if (w >= NNP) return;
    int beg = g_off[w], end = g_off[w + 1];
    const float4* x4 = (const float4*)x;
    float4 a0 = make_float4(0.f, 0.f, 0.f, 0.f);
    float4 a1 = make_float4(0.f, 0.f, 0.f, 0.f);
    int e = beg;
    for (; e + 1 < end; e += 2) {
        int s0 = g_csrc[e], s1 = g_csrc[e + 1];
        float4 v0 = x4[(size_t)s0 * 32 + lane];
        float4 v1 = x4[(size_t)s1 * 32 + lane];
        a0.x += v0.x; a0.y += v0.y; a0.z += v0.z; a0.w += v0.w;
        a1.x += v1.x; a1.y += v1.y; a1.z += v1.z; a1.w += v1.w;
    }
    if (e < end) {
        float4 v = x4[(size_t)g_csrc[e] * 32 + lane];
        a0.x += v.x; a0.y += v.y; a0.z += v.z; a0.w += v.w;
    }
    float inv = g_invdeg[w];
    float4 o;
    o.x = (a0.x + a1.x) * inv;
    o.y = (a0.y + a1.y) * inv;
    o.z = (a0.z + a1.z) * inv;
    o.w = (a0.w + a1.w) * inv;
    ((float4*)g_agg1)[(size_t)w * 32 + lane] = o;
}

// ---------------------------------------------------------------------------
// CSR mean-aggregate p (64 f) -> g_agg2. Warp per node, float2 per lane.
// ---------------------------------------------------------------------------
__global__ void agg2_kernel() {
    int w = (blockIdx.x * blockDim.x + threadIdx.x) >> 5;
    int lane = threadIdx.x & 31;
    if (w >= NN) return;
    int beg = g_off[w], end = g_off[w + 1];
    const float2* p2 = (const float2*)g_p;
    float2 a0 = make_float2(0.f, 0.f);
    float2 a1 = make_float2(0.f, 0.f);
    int e = beg;
    for (; e + 1 < end; e += 2) {
        int s0 = g_csrc[e], s1 = g_csrc[e + 1];
        float2 v0 = p2[(size_t)s0 * 32 + lane];
        float2 v1 = p2[(size_t)s1 * 32 + lane];
        a0.x += v0.x; a0.y += v0.y;
        a1.x += v1.x; a1.y += v1.y;
    }
    if (e < end) {
        float2 v = p2[(size_t)g_csrc[e] * 32 + lane];
        a0.x += v.x; a0.y += v.y;
    }
    float inv = g_invdeg[w];
    float2 o = make_float2((a0.x + a1.x) * inv, (a0.y + a1.y) * inv);
    ((float2*)g_agg2)[(size_t)w * 32 + lane] = o;
}

// ---------------------------------------------------------------------------
// weight pre-transpose + tf32 conversion
// ---------------------------------------------------------------------------
__global__ void wt1_kernel(const float* __restrict__ W1l, const float* __restrict__ W1r) {
    int i = blockIdx.x * blockDim.x + threadIdx.x;   // 32768
    int k = i >> 7, f = i & 127;
    float v = (k < 128) ? W1l[f * 128 + k] : W1r[f * 128 + (k - 128)];
    g_wt1[k * 128 + f] = f2tf(v);
}
__global__ void wt2_kernel(const float* __restrict__ W2l, const float* __restrict__ W2r) {
    int i = blockIdx.x * blockDim.x + threadIdx.x;   // 16384
    int k = i >> 7, f = i & 127;
    float v = (f < 64) ? W2l[f * 128 + k] : W2r[(f - 64) * 128 + k];
    g_wt2[k * 128 + f] = f2tf(v);
}

// ---------------------------------------------------------------------------
// Layer-1 GEMM (tf32 wmma, K=256 concat, cp.async double-buffered):
//   h = relu(BN( [agg1 | x] @ Wt1 + b1 ))
// ---------------------------------------------------------------------------
#define ALD 36
#define WLD 132
#define CLD 136
#define BUFF 8832                       // floats per buffer (As 4608 + Ws 4224)
#define SM1_FLOATS (2 * BUFF + 256)     // buffers (= Cs union) + BN tables
#define SM2_FLOATS (2 * BUFF)

__global__ void __launch_bounds__(256, 2) gemm1_kernel(
    const float* __restrict__ x,
    const float* __restrict__ b1, const float* __restrict__ gmm,
    const float* __restrict__ bet, const float* __restrict__ mean,
    const float* __restrict__ var)
{
    extern __shared__ float sm[];
    float* Cs = sm;                     // union with both buffers
    float* Ssc = sm + 2 * BUFF;
    float* Ssh = Ssc + 128;

    const int tid = threadIdx.x;
    const int wid = tid >> 5;
    const int wm = wid >> 1;
    const int wn = wid & 1;
    const int n0 = blockIdx.x * 128;
    const unsigned smu = (unsigned)__cvta_generic_to_shared(sm);

    if (tid < 128) {
        float s = rsqrtf(var[tid] + 1e-5f) * gmm[tid];
        Ssc[tid] = s;
        Ssh[tid] = (b1[tid] - mean[tid]) * s + bet[tid];
    }

    wmma::fragment<wmma::accumulator, 16, 16, 8, float> acc[2][4];
#pragma unroll
    for (int i = 0; i < 2; i++)
#pragma unroll
        for (int j = 0; j < 4; j++) wmma::fill_fragment(acc[i][j], 0.f);

    const float4* X4 = (const float4*)x;
    const float4* A14 = (const float4*)g_agg1;
    const float4* WT4 = (const float4*)g_wt1;

    auto stage = [&](int kc, int bufi) {
        unsigned base = smu + (unsigned)(bufi * BUFF * 4);
#pragma unroll
        for (int it = 0; it < 4; it++) {
            int t = tid + it * 256;
            int row = t >> 3, q = t & 7;
            int gn = n0 + row;
            unsigned dst = base + (unsigned)((row * ALD + q * 4) * 4);
            if (kc < 4) {
                CPA16(dst, A14 + (size_t)gn * 32 + kc * 8 + q);
            } else {
                int sz = (gn < NN) ? 16 : 0;
                CPA16Z(dst, X4 + (size_t)gn * 32 + (kc - 4) * 8 + q, sz);
            }
        }
#pragma unroll
        for (int it = 0; it < 4; it++) {
            int t = tid + it * 256;
            int kr = t >> 5, fq = t & 31;
            unsigned dst = base + (unsigned)((4608 + kr * WLD + fq * 4) * 4);
            CPA16(dst, WT4 + (kc * 32 + kr) * 32 + fq);
        }
    };

    stage(0, 0);
    CPA_COMMIT();

    for (int kc = 0; kc < 8; kc++) {
        int cur = kc & 1;
        if (kc < 7) stage(kc + 1, cur ^ 1);
        CPA_COMMIT();
        if (kc < 7) CPA_WAIT1(); else CPA_WAIT0();
        __syncthreads();

        float* As = sm + cur * BUFF;
        float* Ws = As + 4608;
#pragma unroll
        for (int k8 = 0; k8 < 4; k8++) {
            wmma::fragment<wmma::matrix_a, 16, 16, 8, wmma::precision::tf32,
                           wmma::row_major> a[2];
#pragma unroll
            for (int i = 0; i < 2; i++) {
                wmma::load_matrix_sync(a[i], As + (wm * 32 + i * 16) * ALD + k8 * 8, ALD);
#pragma unroll
                for (int e = 0; e < a[i].num_elements; e++) a[i].x[e] = f2tf(a[i].x[e]);
            }
#pragma unroll
            for (int nf = 0; nf < 4; nf++) {
                wmma::fragment<wmma::matrix_b, 16, 16, 8, wmma::precision::tf32,
                               wmma::row_major> b;
                wmma::load_matrix_sync(b, Ws + (k8 * 8) * WLD + wn * 64 + nf * 16, WLD);
#pragma unroll
                for (int i = 0; i < 2; i++)
                    wmma::mma_sync(acc[i][nf], a[i], b, acc[i][nf]);
            }
        }
        __syncthreads();
    }

    // epilogue into Cs (buffers dead)
#pragma unroll
    for (int i = 0; i < 2; i++)
#pragma unroll
        for (int nf = 0; nf < 4; nf++)
            wmma::store_matrix_sync(Cs + (wm * 32 + i * 16) * CLD + wn * 64 + nf * 16,
                                    acc[i][nf], CLD, wmma::mem_row_major);
    __syncthreads();
    {
        int row = tid >> 1, half = tid & 1;
        int gn = n0 + row;
        float* dst = g_h + (size_t)gn * HID + half * 64;
        const float* src = Cs + row * CLD + half * 64;
#pragma unroll
        for (int j4 = 0; j4 < 16; j4++) {
            float4 v = *(const float4*)(src + j4 * 4);
            int f = half * 64 + j4 * 4;
            float4 o;
            o.x = fmaxf(v.x * Ssc[f + 0] + Ssh[f + 0], 0.f);
            o.y = fmaxf(v.y * Ssc[f + 1] + Ssh[f + 1], 0.f);
            o.z = fmaxf(v.z * Ssc[f + 2] + Ssh[f + 2], 0.f);
            o.w = fmaxf(v.w * Ssc[f + 3] + Ssh[f + 3], 0.f);
            *(float4*)(dst + j4 * 4) = o;
        }
    }
}

// ---------------------------------------------------------------------------
// Layer-2 fused GEMM: [p | q] = h @ Wt2, direct fragment stores.
// ---------------------------------------------------------------------------
__global__ void __launch_bounds__(256, 2) gemm2_kernel()
{
    extern __shared__ float sm[];
    const int tid = threadIdx.x;
    const int wid = tid >> 5;
    const int wm = wid >> 1;
    const int wn = wid & 1;
    const int n0 = blockIdx.x * 128;
    const unsigned smu = (unsigned)__cvta_generic_to_shared(sm);

    wmma::fragment<wmma::accumulator, 16, 16, 8, float> acc[2][4];
#pragma unroll
    for (int i = 0; i < 2; i++)
#pragma unroll
        for (int j = 0; j < 4; j++) wmma::fill_fragment(acc[i][j], 0.f);

    const float4* H4 = (const float4*)g_h;
    const float4* WT4 = (const float4*)g_wt2;

    auto stage = [&](int kc, int bufi) {
        unsigned base = smu + (unsigned)(bufi * BUFF * 4);
#pragma unroll
        for (int it = 0; it < 4; it++) {
            int t = tid + it * 256;
            int row = t >> 3, q = t & 7;
            unsigned dst = base + (unsigned)((row * ALD + q * 4) * 4);
            CPA16(dst, H4 + (size_t)(n0 + row) * 32 + kc * 8 + q);
        }
#pragma unroll
        for (int it = 0; it < 4; it++) {
            int t = tid + it * 256;
            int kr = t >> 5, fq = t & 31;
            unsigned dst = base + (unsigned)((4608 + kr * WLD + fq * 4) * 4);
            CPA16(dst, WT4 + (kc * 32 + kr) * 32 + fq);
        }
    };

    stage(0, 0);
    CPA_COMMIT();

    for (int kc = 0; kc < 4; kc++) {
        int cur = kc & 1;
        if (kc < 3) stage(kc + 1, cur ^ 1);
        CPA_COMMIT();
        if (kc < 3) CPA_WAIT1(); else CPA_WAIT0();
        __syncthreads();

        float* As = sm + cur * BUFF;
        float* Ws = As + 4608;
#pragma unroll
        for (int k8 = 0; k8 < 4; k8++) {
            wmma::fragment<wmma::matrix_a, 16, 16, 8, wmma::precision::tf32,
                           wmma::row_major> a[2];
#pragma unroll
            for (int i = 0; i < 2; i++) {
                wmma::load_matrix_sync(a[i], As + (wm * 32 + i * 16) * ALD + k8 * 8, ALD);
#pragma unroll
                for (int e = 0; e < a[i].num_elements; e++) a[i].x[e] = f2tf(a[i].x[e]);
            }
#pragma unroll
            for (int nf = 0; nf < 4; nf++) {
                wmma::fragment<wmma::matrix_b, 16, 16, 8, wmma::precision::tf32,
                               wmma::row_major> b;
                wmma::load_matrix_sync(b, Ws + (k8 * 8) * WLD + wn * 64 + nf * 16, WLD);
#pragma unroll
                for (int i = 0; i < 2; i++)
                    wmma::mma_sync(acc[i][nf], a[i], b, acc[i][nf]);
            }
        }
        __syncthreads();
    }

    float* base = wn ? g_q : g_p;
#pragma unroll
    for (int i = 0; i < 2; i++)
#pragma unroll
        for (int nf = 0; nf < 4; nf++)
            wmma::store_matrix_sync(
                base + (size_t)(n0 + wm * 32 + i * 16) * OF + nf * 16,
                acc[i][nf], OF, wmma::mem_row_major);
}

// ---------------------------------------------------------------------------
// Final: out = q + agg2 + b2   (agg2 already mean)
// ---------------------------------------------------------------------------
__global__ void final_kernel(const float* __restrict__ b2, float* __restrict__ out) {
    int t = blockIdx.x * blockDim.x + threadIdx.x;
    if (t >= NN * 16) return;
    int n = t >> 4, j = t & 15;
    float4 q = ((const float4*)g_q)[(size_t)n * 16 + j];
    float4 a = ((const float4*)g_agg2)[(size_t)n * 16 + j];
    float4 bb = ((const float4*)b2)[j];
    float4 o;
    o.x = q.x + a.x + bb.x;
    o.y = q.y + a.y + bb.y;
    o.z = q.z + a.z + bb.z;
    o.w = q.w + a.w + bb.w;
    ((float4*)out)[(size_t)n * 16 + j] = o;
}

// ---------------------------------------------------------------------------
// Launch
// ---------------------------------------------------------------------------
extern "C" void kernel_launch(void* const* d_in, const int* in_sizes, int n_in,
                              void* d_out, int out_size) {
    const float* x    = (const float*)d_in[0];
    const void*  ei   = d_in[1];
    const float* W1l  = (const float*)d_in[2];
    const float* b1   = (const float*)d_in[3];
    const float* W1r  = (const float*)d_in[4];
    const float* gmm  = (const float*)d_in[5];
    const float* bet  = (const float*)d_in[6];
    const float* mean = (const float*)d_in[7];
    const float* var  = (const float*)d_in[8];
    const float* W2l  = (const float*)d_in[9];
    const float* b2   = (const float*)d_in[10];
    const float* W2r  = (const float*)d_in[11];
    float* out = (float*)d_out;

    const int SM1 = SM1_FLOATS * 4;
    const int SM2 = SM2_FLOATS * 4;
    cudaFuncSetAttribute(gemm1_kernel, cudaFuncAttributeMaxDynamicSharedMemorySize, SM1);
    cudaFuncSetAttribute(gemm2_kernel, cudaFuncAttributeMaxDynamicSharedMemorySize, SM2);

    void* degp = 0;
    cudaGetSymbolAddress(&degp, g_deg);

    detect_kernel<<<1, 256>>>((const int*)ei);
    cudaMemsetAsync(degp, 0, sizeof(int) * NNP, 0);
    wt1_kernel<<<128, 256>>>(W1l, W1r);
    wt2_kernel<<<64, 256>>>(W2l, W2r);

    deg_kernel<<<(NE + 255) / 256, 256>>>(ei);
    invdeg_kernel<<<(NNP + 255) / 256, 256>>>();
    scan1_kernel<<<NNP / 128, 128>>>();
    scan2_kernel<<<1, 1024>>>(NNP / 128);
    scan3_kernel<<<NNP / 128, 128>>>();
    cur_kernel<<<(NNP + 255) / 256, 256>>>();
    sort_kernel<<<(NE + 255) / 256, 256>>>(ei);

    agg1_kernel<<<NNP / 8, 256>>>(x);

    const int NB = NNP / 128;  // 782
    gemm1_kernel<<<NB, 256, SM1>>>(x, b1, gmm, bet, mean, var);
    gemm2_kernel<<<NB, 256, SM2>>>();
    agg2_kernel<<<NN / 8, 256>>>();
    final_kernel<<<(NN * 16 + 255) / 256, 256>>>(b2, out);
}

// round 5
// speedup vs baseline: 1.8546x; 1.0069x over previous
#include <cuda_runtime.h>
#include <cuda_fp16.h>
#include <mma.h>
using namespace nvcuda;

#define NN 100000
#define NNP 100096           // 782*128
#define NE 1600000
#define HID 128
#define OF 64

// ---------------- scratch (device globals; no allocation allowed) ----------
__device__ float  g_agg1[NNP * HID];  // mean aggregation of x (invdeg folded)
__device__ float  g_h[NNP * HID];     // layer-1 output (post BN+ReLU)
__device__ __half g_x16[NN * HID];    // fp16 copy of x (gather source)
__device__ __half g_p16[NNP * OF];    // h @ W2_l.T in fp16 (gather source)
__device__ float  g_q[NNP * OF];      // h @ W2_r.T
__device__ float  g_wt1[256 * HID];   // [W1l;W1r] transposed [k][f], tf32
__device__ float  g_wt2[HID * HID];   // [W2l|W2r] transposed [k][f], tf32
__device__ int    g_deg[NNP];
__device__ float  g_invdeg[NNP];
__device__ int    g_off[NNP + 1];     // CSR offsets (by dst)
__device__ int    g_cur[NNP];         // counting-sort cursors
__device__ int    g_csrc[NE];         // src sorted by dst
__device__ int    g_tmp[NNP];         // block-local inclusive scans
__device__ int    g_bsum[1024];
__device__ int    g_boff[1024];
__device__ int    g_is64;

__device__ __forceinline__ float f2tf(float v) {
    unsigned u;
    asm("cvt.rna.tf32.f32 %0, %1;" : "=r"(u) : "f"(v));
    return __uint_as_float(u);
}

#define CPA16(dst, src) \
    asm volatile("cp.async.cg.shared.global [%0], [%1], 16;" :: "r"(dst), "l"(src))
#define CPA16Z(dst, src, sz) \
    asm volatile("cp.async.cg.shared.global [%0], [%1], 16, %2;" :: "r"(dst), "l"(src), "r"(sz))
#define CPA_COMMIT() asm volatile("cp.async.commit_group;")
#define CPA_WAIT1()  asm volatile("cp.async.wait_group 1;")
#define CPA_WAIT0()  asm volatile("cp.async.wait_group 0;")

// ---------------------------------------------------------------------------
// dtype detection: int64 edge_index <=> hi words of first 256 entries all 0
// ---------------------------------------------------------------------------
__global__ void detect_kernel(const int* ei32) {
    __shared__ int cnt;
    if (threadIdx.x == 0) cnt = 0;
    __syncthreads();
    if (ei32[2 * threadIdx.x + 1] != 0) atomicAdd(&cnt, 1);
    __syncthreads();
    if (threadIdx.x == 0) g_is64 = (cnt == 0) ? 1 : 0;
}

__device__ __forceinline__ int ld_edge(const void* ei, long long idx, int is64) {
    return is64 ? (int)((const long long*)ei)[idx] : ((const int*)ei)[idx];
}

// ---------------------------------------------------------------------------
// x -> fp16 copy (gather source)
// ---------------------------------------------------------------------------
__global__ void x16_kernel(const float* __restrict__ x) {
    int i = blockIdx.x * blockDim.x + threadIdx.x;   // NN*32 float4 chunks
    if (i >= NN * 32) return;
    float4 v = ((const float4*)x)[i];
    __half2 h0 = __floats2half2_rn(v.x, v.y);
    __half2 h1 = __floats2half2_rn(v.z, v.w);
    uint2 u;
    u.x = *(unsigned*)&h0;
    u.y = *(unsigned*)&h1;
    ((uint2*)g_x16)[i] = u;
}

// ---------------------------------------------------------------------------
// degree count (thread per edge, int atomics only)
// ---------------------------------------------------------------------------
__global__ void deg_kernel(const void* ei) {
    int e = blockIdx.x * blockDim.x + threadIdx.x;
    if (e < NE) {
        int dst = ld_edge(ei, (long long)NE + e, g_is64);
        atomicAdd(&g_deg[dst], 1);
    }
}

// ---------------------------------------------------------------------------
// 3-phase exclusive scan of degrees -> g_off (+cursors +invdeg fused)
// ---------------------------------------------------------------------------
__global__ void scan1_kernel() {
    __shared__ int s[128];
    int i = blockIdx.x * 128 + threadIdx.x;
    int t = threadIdx.x;
    s[t] = g_deg[i];
    __syncthreads();
    for (int o = 1; o < 128; o <<= 1) {
        int v = (t >= o) ? s[t - o] : 0;
        __syncthreads();
        s[t] += v;
        __syncthreads();
    }
    g_tmp[i] = s[t];
    if (t == 127) g_bsum[blockIdx.x] = s[127];
}
__global__ void scan2_kernel(int nb) {
    __shared__ int s[1024];
    int t = threadIdx.x;
    int own = (t < nb) ? g_bsum[t] : 0;
    s[t] = own;
    __syncthreads();
    for (int o = 1; o < 1024; o <<= 1) {
        int v = (t >= o) ? s[t - o] : 0;
        __syncthreads();
        s[t] += v;
        __syncthreads();
    }
    if (t < nb) g_boff[t] = s[t] - own;   // exclusive
}
__global__ void scan3_kernel() {
    int i = blockIdx.x * 128 + threadIdx.x;
    int d = g_deg[i];
    int incl = g_tmp[i] + g_boff[blockIdx.x];
    g_off[i + 1] = incl;
    g_cur[i] = incl - d;                  // exclusive offset = cursor start
    g_invdeg[i] = 1.0f / fmaxf((float)d, 1.0f);
    if (i == 0) g_off[0] = 0;
}

// ---------------------------------------------------------------------------
// counting sort: csrc sorted by dst
// ---------------------------------------------------------------------------
__global__ void sort_kernel(const void* ei) {
    int e = blockIdx.x * blockDim.x + threadIdx.x;
    if (e < NE) {
        int is64 = g_is64;
        int src = ld_edge(ei, e, is64);
        int dst = ld_edge(ei, (long long)NE + e, is64);
        int pos = atomicAdd(&g_cur[dst], 1);
        g_csrc[pos] = src;
    }
}

// ---------------------------------------------------------------------------
// CSR mean-aggregate x16 (128 halfs) -> g_agg1 fp32. Warp per node.
// Lane owns 4 features (uint2 = 4 halfs). 4-edge unroll for MLP.
// ---------------------------------------------------------------------------
__global__ void agg1_kernel() {
    int w = (blockIdx.x * blockDim.x + threadIdx.x) >> 5;
    int lane = threadIdx.x & 31;
    if (w >= NNP) return;
    int beg = g_off[w], end = g_off[w + 1];
    const uint2* X = (const uint2*)g_x16;   // row = 32 uint2
    float a0 = 0.f, a1 = 0.f, a2 = 0.f, a3 = 0.f;
    float b0 = 0.f, b1 = 0.f, b2 = 0.f, b3 = 0.f;
    int e = beg;
    for (; e + 3 < end; e += 4) {
        int s0 = g_csrc[e], s1 = g_csrc[e + 1], s2 = g_csrc[e + 2], s3 = g_csrc[e + 3];
        uint2 u0 = __ldg(&X[(size_t)s0 * 32 + lane]);
        uint2 u1 = __ldg(&X[(size_t)s1 * 32 + lane]);
        uint2 u2 = __ldg(&X[(size_t)s2 * 32 + lane]);
        uint2 u3 = __ldg(&X[(size_t)s3 * 32 + lane]);
        float2 f;
        f = __half22float2(*(__half2*)&u0.x); a0 += f.x; a1 += f.y;
        f = __half22float2(*(__half2*)&u0.y); a2 += f.x; a3 += f.y;
        f = __half22float2(*(__half2*)&u1.x); b0 += f.x; b1 += f.y;
        f = __half22float2(*(__half2*)&u1.y); b2 += f.x; b3 += f.y;
        f = __half22float2(*(__half2*)&u2.x); a0 += f.x; a1 += f.y;
        f = __half22float2(*(__half2*)&u2.y); a2 += f.x; a3 += f.y;
        f = __half22float2(*(__half2*)&u3.x); b0 += f.x; b1 += f.y;
        f = __half22float2(*(__half2*)&u3.y); b2 += f.x; b3 += f.y;
    }
    for (; e < end; e++) {
        uint2 u = __ldg(&X[(size_t)g_csrc[e] * 32 + lane]);
        float2 f;
        f = __half22float2(*(__half2*)&u.x); a0 += f.x; a1 += f.y;
        f = __half22float2(*(__half2*)&u.y); a2 += f.x; a3 += f.y;
    }
    float inv = g_invdeg[w];
    float4 o = make_float4((a0 + b0) * inv, (a1 + b1) * inv,
                           (a2 + b2) * inv, (a3 + b3) * inv);
    ((float4*)g_agg1)[(size_t)w * 32 + lane] = o;
}

// ---------------------------------------------------------------------------
// CSR mean-aggregate p16 (64 halfs) + q + b2 -> out. Warp per node.
// Lane owns 2 features (one half2 / one float2 of q).
// ---------------------------------------------------------------------------
__global__ void agg2_final_kernel(const float* __restrict__ b2,
                                  float* __restrict__ out) {
    int w = (blockIdx.x * blockDim.x + threadIdx.x) >> 5;
    int lane = threadIdx.x & 31;
    if (w >= NN) return;
    int beg = g_off[w], end = g_off[w + 1];
    const unsigned* P = (const unsigned*)g_p16;   // row = 32 half2
    float a0 = 0.f, a1 = 0.f, b0 = 0.f, b1 = 0.f;
    int e = beg;
    for (; e + 3 < end; e += 4) {
        int s0 = g_csrc[e], s1 = g_csrc[e + 1], s2 = g_csrc[e + 2], s3 = g_csrc[e + 3];
        unsigned u0 = __ldg(&P[(size_t)s0 * 32 + lane]);
        unsigned u1 = __ldg(&P[(size_t)s1 * 32 + lane]);
        unsigned u2 = __ldg(&P[(size_t)s2 * 32 + lane]);
        unsigned u3 = __ldg(&P[(size_t)s3 * 32 + lane]);
        float2 f;
        f = __half22float2(*(__half2*)&u0); a0 += f.x; a1 += f.y;
        f = __half22float2(*(__half2*)&u1); b0 += f.x; b1 += f.y;
        f = __half22float2(*(__half2*)&u2); a0 += f.x; a1 += f.y;
        f = __half22float2(*(__half2*)&u3); b0 += f.x; b1 += f.y;
    }
    for (; e < end; e++) {
        unsigned u = __ldg(&P[(size_t)g_csrc[e] * 32 + lane]);
        float2 f = __half22float2(*(__half2*)&u);
        a0 += f.x; a1 += f.y;
    }
    float inv = g_invdeg[w];
    float2 q = ((const float2*)g_q)[(size_t)w * 32 + lane];
    float2 bb = ((const float2*)b2)[lane];
    float2 o = make_float2((a0 + b0) * inv + q.x + bb.x,
                           (a1 + b1) * inv + q.y + bb.y);
    ((float2*)out)[(size_t)w * 32 + lane] = o;
}

// ---------------------------------------------------------------------------
// weight pre-transpose + tf32 conversion
// ---------------------------------------------------------------------------
__global__ void wt1_kernel(const float* __restrict__ W1l, const float* __restrict__ W1r) {
    int i = blockIdx.x * blockDim.x + threadIdx.x;   // 32768
    int k = i >> 7, f = i & 127;
    float v = (k < 128) ? W1l[f * 128 + k] : W1r[f * 128 + (k - 128)];
    g_wt1[k * 128 + f] = f2tf(v);
}
__global__ void wt2_kernel(const float* __restrict__ W2l, const float* __restrict__ W2r) {
    int i = blockIdx.x * blockDim.x + threadIdx.x;   // 16384
    int k = i >> 7, f = i & 127;
    float v = (f < 64) ? W2l[f * 128 + k] : W2r[(f - 64) * 128 + k];
    g_wt2[k * 128 + f] = f2tf(v);
}

// ---------------------------------------------------------------------------
// Layer-1 GEMM (tf32 wmma, K=256 concat, cp.async double-buffered):
//   h = relu(BN( [agg1 | x] @ Wt1 + b1 ))
// ---------------------------------------------------------------------------
#define ALD 36
#define WLD 132
#define CLD 136
#define BUFF 8832                       // floats per buffer (As 4608 + Ws 4224)
#define SM1_FLOATS (2 * BUFF + 256)
#define SM2_FLOATS (2 * BUFF)

__global__ void __launch_bounds__(256, 2) gemm1_kernel(
    const float* __restrict__ x,
    const float* __restrict__ b1, const float* __restrict__ gmm,
    const float* __restrict__ bet, const float* __restrict__ mean,
    const float* __restrict__ var)
{
    extern __shared__ float sm[];
    float* Cs = sm;
    float* Ssc = sm + 2 * BUFF;
    float* Ssh = Ssc + 128;

    const int tid = threadIdx.x;
    const int wid = tid >> 5;
    const int wm = wid >> 1;
    const int wn = wid & 1;
    const int n0 = blockIdx.x * 128;
    const unsigned smu = (unsigned)__cvta_generic_to_shared(sm);

    if (tid < 128) {
        float s = rsqrtf(var[tid] + 1e-5f) * gmm[tid];
        Ssc[tid] = s;
        Ssh[tid] = (b1[tid] - mean[tid]) * s + bet[tid];
    }

    wmma::fragment<wmma::accumulator, 16, 16, 8, float> acc[2][4];
#pragma unroll
    for (int i = 0; i < 2; i++)
#pragma unroll
        for (int j = 0; j < 4; j++) wmma::fill_fragment(acc[i][j], 0.f);

    const float4* X4 = (const float4*)x;
    const float4* A14 = (const float4*)g_agg1;
    const float4* WT4 = (const float4*)g_wt1;

    auto stage = [&](int kc, int bufi) {
        unsigned base = smu + (unsigned)(bufi * BUFF * 4);
#pragma unroll
        for (int it = 0; it < 4; it++) {
            int t = tid + it * 256;
            int row = t >> 3, q = t & 7;
            int gn = n0 + row;
            unsigned dst = base + (unsigned)((row * ALD + q * 4) * 4);
            if (kc < 4) {
                CPA16(dst, A14 + (size_t)gn * 32 + kc * 8 + q);
            } else {
                int sz = (gn < NN) ? 16 : 0;
                CPA16Z(dst, X4 + (size_t)gn * 32 + (kc - 4) * 8 + q, sz);
            }
        }
#pragma unroll
        for (int it = 0; it < 4; it++) {
            int t = tid + it * 256;
            int kr = t >> 5, fq = t & 31;
            unsigned dst = base + (unsigned)((4608 + kr * WLD + fq * 4) * 4);
            CPA16(dst, WT4 + (kc * 32 + kr) * 32 + fq);
        }
    };

    stage(0, 0);
    CPA_COMMIT();

    for (int kc = 0; kc < 8; kc++) {
        int cur = kc & 1;
        if (kc < 7) stage(kc + 1, cur ^ 1);
        CPA_COMMIT();
        if (kc < 7) CPA_WAIT1(); else CPA_WAIT0();
        __syncthreads();

        float* As = sm + cur * BUFF;
        float* Ws = As + 4608;
#pragma unroll
        for (int k8 = 0; k8 < 4; k8++) {
            wmma::fragment<wmma::matrix_a, 16, 16, 8, wmma::precision::tf32,
                           wmma::row_major> a[2];
#pragma unroll
            for (int i = 0; i < 2; i++) {
                wmma::load_matrix_sync(a[i], As + (wm * 32 + i * 16) * ALD + k8 * 8, ALD);
#pragma unroll
                for (int e = 0; e < a[i].num_elements; e++) a[i].x[e] = f2tf(a[i].x[e]);
            }
#pragma unroll
            for (int nf = 0; nf < 4; nf++) {
                wmma::fragment<wmma::matrix_b, 16, 16, 8, wmma::precision::tf32,
                               wmma::row_major> b;
                wmma::load_matrix_sync(b, Ws + (k8 * 8) * WLD + wn * 64 + nf * 16, WLD);
#pragma unroll
                for (int i = 0; i < 2; i++)
                    wmma::mma_sync(acc[i][nf], a[i], b, acc[i][nf]);
            }
        }
        __syncthreads();
    }

#pragma unroll
    for (int i = 0; i < 2; i++)
#pragma unroll
        for (int nf = 0; nf < 4; nf++)
            wmma::store_matrix_sync(Cs + (wm * 32 + i * 16) * CLD + wn * 64 + nf * 16,
                                    acc[i][nf], CLD, wmma::mem_row_major);
    __syncthreads();
    {
        int row = tid >> 1, half = tid & 1;
        int gn = n0 + row;
        float* dst = g_h + (size_t)gn * HID + half * 64;
        const float* src = Cs + row * CLD + half * 64;
#pragma unroll
        for (int j4 = 0; j4 < 16; j4++) {
            float4 v = *(const float4*)(src + j4 * 4);
            int f = half * 64 + j4 * 4;
            float4 o;
            o.x = fmaxf(v.x * Ssc[f + 0] + Ssh[f + 0], 0.f);
            o.y = fmaxf(v.y * Ssc[f + 1] + Ssh[f + 1], 0.f);
            o.z = fmaxf(v.z * Ssc[f + 2] + Ssh[f + 2], 0.f);
            o.w = fmaxf(v.w * Ssc[f + 3] + Ssh[f + 3], 0.f);
            *(float4*)(dst + j4 * 4) = o;
        }
    }
}

// ---------------------------------------------------------------------------
// Layer-2 fused GEMM: [p | q] = h @ Wt2.  p -> fp16 (g_p16), q -> fp32 (g_q).
// ---------------------------------------------------------------------------
__global__ void __launch_bounds__(256, 2) gemm2_kernel()
{
    extern __shared__ float sm[];
    float* Cs = sm;
    const int tid = threadIdx.x;
    const int wid = tid >> 5;
    const int wm = wid >> 1;
    const int wn = wid & 1;
    const int n0 = blockIdx.x * 128;
    const unsigned smu = (unsigned)__cvta_generic_to_shared(sm);

    wmma::fragment<wmma::accumulator, 16, 16, 8, float> acc[2][4];
#pragma unroll
    for (int i = 0; i < 2; i++)
#pragma unroll
        for (int j = 0; j < 4; j++) wmma::fill_fragment(acc[i][j], 0.f);

    const float4* H4 = (const float4*)g_h;
    const float4* WT4 = (const float4*)g_wt2;

    auto stage = [&](int kc, int bufi) {
        unsigned base = smu + (unsigned)(bufi * BUFF * 4);
#pragma unroll
        for (int it = 0; it < 4; it++) {
            int t = tid + it * 256;
            int row = t >> 3, q = t & 7;
            unsigned dst = base + (unsigned)((row * ALD + q * 4) * 4);
            CPA16(dst, H4 + (size_t)(n0 + row) * 32 + kc * 8 + q);
        }
#pragma unroll
        for (int it = 0; it < 4; it++) {
            int t = tid + it * 256;
            int kr = t >> 5, fq = t & 31;
            unsigned dst = base + (unsigned)((4608 + kr * WLD + fq * 4) * 4);
            CPA16(dst, WT4 + (kc * 32 + kr) * 32 + fq);
        }
    };

    stage(0, 0);
    CPA_COMMIT();

    for (int kc = 0; kc < 4; kc++) {
        int cur = kc & 1;
        if (kc < 3) stage(kc + 1, cur ^ 1);
        CPA_COMMIT();
        if (kc < 3) CPA_WAIT1(); else CPA_WAIT0();
        __syncthreads();

        float* As = sm + cur * BUFF;
        float* Ws = As + 4608;
#pragma unroll
        for (int k8 = 0; k8 < 4; k8++) {
            wmma::fragment<wmma::matrix_a, 16, 16, 8, wmma::precision::tf32,
                           wmma::row_major> a[2];
#pragma unroll
            for (int i = 0; i < 2; i++) {
                wmma::load_matrix_sync(a[i], As + (wm * 32 + i * 16) * ALD + k8 * 8, ALD);
#pragma unroll
                for (int e = 0; e < a[i].num_elements; e++) a[i].x[e] = f2tf(a[i].x[e]);
            }
#pragma unroll
            for (int nf = 0; nf < 4; nf++) {
                wmma::fragment<wmma::matrix_b, 16, 16, 8, wmma::precision::tf32,
                               wmma::row_major> b;
                wmma::load_matrix_sync(b, Ws + (k8 * 8) * WLD + wn * 64 + nf * 16, WLD);
#pragma unroll
                for (int i = 0; i < 2; i++)
                    wmma::mma_sync(acc[i][nf], a[i], b, acc[i][nf]);
            }
        }
        __syncthreads();
    }

    // epilogue through smem: p cols [0,64) -> fp16, q cols [64,128) -> fp32
#pragma unroll
    for (int i = 0; i < 2; i++)
#pragma unroll
        for (int nf = 0; nf < 4; nf++)
            wmma::store_matrix_sync(Cs + (wm * 32 + i * 16) * CLD + wn * 64 + nf * 16,
                                    acc[i][nf], CLD, wmma::mem_row_major);
    __syncthreads();
    {
        int row = tid >> 1, half = tid & 1;
        int gn = n0 + row;
        const float* src = Cs + row * CLD + half * 64;
        if (half == 0) {
            uint2* dst = (uint2*)(g_p16 + (size_t)gn * OF);
#pragma unroll
            for (int j = 0; j < 16; j++) {
                float4 v = *(const float4*)(src + j * 4);
                __half2 h0 = __floats2half2_rn(v.x, v.y);
                __half2 h1 = __floats2half2_rn(v.z, v.w);
                uint2 u;
                u.x = *(unsigned*)&h0;
                u.y = *(unsigned*)&h1;
                dst[j] = u;
            }
        } else {
            float4* dst = (float4*)(g_q + (size_t)gn * OF);
#pragma unroll
            for (int j = 0; j < 16; j++)
                dst[j] = *(const float4*)(src + j * 4);
        }
    }
}

// ---------------------------------------------------------------------------
// Launch
// ---------------------------------------------------------------------------
extern "C" void kernel_launch(void* const* d_in, const int* in_sizes, int n_in,
                              void* d_out, int out_size) {
    const float* x    = (const float*)d_in[0];
    const void*  ei   = d_in[1];
    const float* W1l  = (const float*)d_in[2];
    const float* b1   = (const float*)d_in[3];
    const float* W1r  = (const float*)d_in[4];
    const float* gmm  = (const float*)d_in[5];
    const float* bet  = (const float*)d_in[6];
    const float* mean = (const float*)d_in[7];
    const float* var  = (const float*)d_in[8];
    const float* W2l  = (const float*)d_in[9];
    const float* b2   = (const float*)d_in[10];
    const float* W2r  = (const float*)d_in[11];
    float* out = (float*)d_out;

    const int SM1 = SM1_FLOATS * 4;
    const int SM2 = SM2_FLOATS * 4;
    cudaFuncSetAttribute(gemm1_kernel, cudaFuncAttributeMaxDynamicSharedMemorySize, SM1);
    cudaFuncSetAttribute(gemm2_kernel, cudaFuncAttributeMaxDynamicSharedMemorySize, SM2);

    void* degp = 0;
    cudaGetSymbolAddress(&degp, g_deg);

    detect_kernel<<<1, 256>>>((const int*)ei);
    cudaMemsetAsync(degp, 0, sizeof(int) * NNP, 0);
    wt1_kernel<<<128, 256>>>(W1l, W1r);
    wt2_kernel<<<64, 256>>>(W2l, W2r);
    x16_kernel<<<(NN * 32 + 255) / 256, 256>>>(x);

    deg_kernel<<<(NE + 255) / 256, 256>>>(ei);
    scan1_kernel<<<NNP / 128, 128>>>();
    scan2_kernel<<<1, 1024>>>(NNP / 128);
    scan3_kernel<<<NNP / 128, 128>>>();
    sort_kernel<<<(NE + 255) / 256, 256>>>(ei);

    agg1_kernel<<<NNP / 8, 256>>>();

    const int NB = NNP / 128;  // 782
    gemm1_kernel<<<NB, 256, SM1>>>(x, b1, gmm, bet, mean, var);
    gemm2_kernel<<<NB, 256, SM2>>>();
    agg2_final_kernel<<<NN / 8, 256>>>(b2, out);
}

// round 6
// speedup vs baseline: 2.8222x; 1.5217x over previous
#include <cuda_runtime.h>
#include <cuda_fp16.h>
#include <mma.h>
using namespace nvcuda;

#define NN 100000
#define NNP 100096           // 782*128
#define NE 1600000
#define HID 128
#define OF 64

// ---------------- scratch (device globals; no allocation allowed) ----------
__device__ __half g_x16[NN * HID];    // fp16 copy of x (gather + GEMM source)
__device__ __half g_a16[NNP * HID];   // mean aggregation of x, fp16
__device__ __half g_h16[NNP * HID];   // layer-1 output, fp16
__device__ __half g_p16[NNP * OF];    // h @ W2_l.T, fp16 (gather source)
__device__ float  g_q[NNP * OF];      // h @ W2_r.T, fp32
__device__ __half g_wt1h[256 * HID];  // [W1l;W1r] transposed [k][f], fp16
__device__ __half g_wt2h[HID * HID];  // [W2l|W2r] transposed [k][f], fp16
__device__ int    g_deg[NNP];
__device__ float  g_invdeg[NNP];
__device__ int    g_off[NNP + 1];     // CSR offsets (by dst)
__device__ int    g_cur[NNP];         // counting-sort cursors
__device__ int    g_csrc[NE];         // src sorted by dst
__device__ int    g_tmp[NNP];
__device__ int    g_bsum[1024];
__device__ int    g_boff[1024];
__device__ int    g_is64;

#define CPA16(dst, src) \
    asm volatile("cp.async.cg.shared.global [%0], [%1], 16;" :: "r"(dst), "l"(src))
#define CPA16Z(dst, src, sz) \
    asm volatile("cp.async.cg.shared.global [%0], [%1], 16, %2;" :: "r"(dst), "l"(src), "r"(sz))
#define CPA_COMMIT() asm volatile("cp.async.commit_group;")
#define CPA_WAIT1()  asm volatile("cp.async.wait_group 1;")
#define CPA_WAIT0()  asm volatile("cp.async.wait_group 0;")

// ---------------------------------------------------------------------------
// dtype detection: int64 edge_index <=> hi words of first 256 entries all 0
// ---------------------------------------------------------------------------
__global__ void detect_kernel(const int* ei32) {
    __shared__ int cnt;
    if (threadIdx.x == 0) cnt = 0;
    __syncthreads();
    if (ei32[2 * threadIdx.x + 1] != 0) atomicAdd(&cnt, 1);
    __syncthreads();
    if (threadIdx.x == 0) g_is64 = (cnt == 0) ? 1 : 0;
}

__device__ __forceinline__ int ld_edge(const void* ei, long long idx, int is64) {
    return is64 ? (int)((const long long*)ei)[idx] : ((const int*)ei)[idx];
}

// ---------------------------------------------------------------------------
// x -> fp16
// ---------------------------------------------------------------------------
__global__ void x16_kernel(const float* __restrict__ x) {
    int i = blockIdx.x * blockDim.x + threadIdx.x;   // NN*32 float4 chunks
    if (i >= NN * 32) return;
    float4 v = ((const float4*)x)[i];
    __half2 h0 = __floats2half2_rn(v.x, v.y);
    __half2 h1 = __floats2half2_rn(v.z, v.w);
    uint2 u;
    u.x = *(unsigned*)&h0;
    u.y = *(unsigned*)&h1;
    ((uint2*)g_x16)[i] = u;
}

// ---------------------------------------------------------------------------
// degree count
// ---------------------------------------------------------------------------
__global__ void deg_kernel(const void* ei) {
    int e = blockIdx.x * blockDim.x + threadIdx.x;
    if (e < NE) {
        int dst = ld_edge(ei, (long long)NE + e, g_is64);
        atomicAdd(&g_deg[dst], 1);
    }
}

// ---------------------------------------------------------------------------
// 3-phase exclusive scan of degrees -> g_off (+cursors +invdeg fused)
// ---------------------------------------------------------------------------
__global__ void scan1_kernel() {
    __shared__ int s[128];
    int i = blockIdx.x * 128 + threadIdx.x;
    int t = threadIdx.x;
    s[t] = g_deg[i];
    __syncthreads();
    for (int o = 1; o < 128; o <<= 1) {
        int v = (t >= o) ? s[t - o] : 0;
        __syncthreads();
        s[t] += v;
        __syncthreads();
    }
    g_tmp[i] = s[t];
    if (t == 127) g_bsum[blockIdx.x] = s[127];
}
__global__ void scan2_kernel(int nb) {
    __shared__ int s[1024];
    int t = threadIdx.x;
    int own = (t < nb) ? g_bsum[t] : 0;
    s[t] = own;
    __syncthreads();
    for (int o = 1; o < 1024; o <<= 1) {
        int v = (t >= o) ? s[t - o] : 0;
        __syncthreads();
        s[t] += v;
        __syncthreads();
    }
    if (t < nb) g_boff[t] = s[t] - own;   // exclusive
}
__global__ void scan3_kernel() {
    int i = blockIdx.x * 128 + threadIdx.x;
    int d = g_deg[i];
    int incl = g_tmp[i] + g_boff[blockIdx.x];
    g_off[i + 1] = incl;
    g_cur[i] = incl - d;
    g_invdeg[i] = 1.0f / fmaxf((float)d, 1.0f);
    if (i == 0) g_off[0] = 0;
}

// ---------------------------------------------------------------------------
// counting sort: csrc sorted by dst
// ---------------------------------------------------------------------------
__global__ void sort_kernel(const void* ei) {
    int e = blockIdx.x * blockDim.x + threadIdx.x;
    if (e < NE) {
        int is64 = g_is64;
        int src = ld_edge(ei, e, is64);
        int dst = ld_edge(ei, (long long)NE + e, is64);
        int pos = atomicAdd(&g_cur[dst], 1);
        g_csrc[pos] = src;
    }
}

// ---------------------------------------------------------------------------
// CSR mean-aggregate x16 -> g_a16 (fp16, fp32 accum). Warp per node.
// ---------------------------------------------------------------------------
__global__ void agg1_kernel() {
    int w = (blockIdx.x * blockDim.x + threadIdx.x) >> 5;
    int lane = threadIdx.x & 31;
    if (w >= NNP) return;
    int beg = g_off[w], end = g_off[w + 1];
    const uint2* X = (const uint2*)g_x16;   // row = 32 uint2
    float a0 = 0.f, a1 = 0.f, a2 = 0.f, a3 = 0.f;
    float b0 = 0.f, b1 = 0.f, b2 = 0.f, b3 = 0.f;
    int e = beg;
    for (; e + 3 < end; e += 4) {
        int s0 = g_csrc[e], s1 = g_csrc[e + 1], s2 = g_csrc[e + 2], s3 = g_csrc[e + 3];
        uint2 u0 = __ldg(&X[(size_t)s0 * 32 + lane]);
        uint2 u1 = __ldg(&X[(size_t)s1 * 32 + lane]);
        uint2 u2 = __ldg(&X[(size_t)s2 * 32 + lane]);
        uint2 u3 = __ldg(&X[(size_t)s3 * 32 + lane]);
        float2 f;
        f = __half22float2(*(__half2*)&u0.x); a0 += f.x; a1 += f.y;
        f = __half22float2(*(__half2*)&u0.y); a2 += f.x; a3 += f.y;
        f = __half22float2(*(__half2*)&u1.x); b0 += f.x; b1 += f.y;
        f = __half22float2(*(__half2*)&u1.y); b2 += f.x; b3 += f.y;
        f = __half22float2(*(__half2*)&u2.x); a0 += f.x; a1 += f.y;
        f = __half22float2(*(__half2*)&u2.y); a2 += f.x; a3 += f.y;
        f = __half22float2(*(__half2*)&u3.x); b0 += f.x; b1 += f.y;
        f = __half22float2(*(__half2*)&u3.y); b2 += f.x; b3 += f.y;
    }
    for (; e < end; e++) {
        uint2 u = __ldg(&X[(size_t)g_csrc[e] * 32 + lane]);
        float2 f;
        f = __half22float2(*(__half2*)&u.x); a0 += f.x; a1 += f.y;
        f = __half22float2(*(__half2*)&u.y); a2 += f.x; a3 += f.y;
    }
    float inv = g_invdeg[w];
    __half2 h0 = __floats2half2_rn((a0 + b0) * inv, (a1 + b1) * inv);
    __half2 h1 = __floats2half2_rn((a2 + b2) * inv, (a3 + b3) * inv);
    uint2 o;
    o.x = *(unsigned*)&h0;
    o.y = *(unsigned*)&h1;
    ((uint2*)g_a16)[(size_t)w * 32 + lane] = o;
}

// ---------------------------------------------------------------------------
// CSR mean-aggregate p16 + q + b2 -> out. Warp per node.
// ---------------------------------------------------------------------------
__global__ void agg2_final_kernel(const float* __restrict__ b2,
                                  float* __restrict__ out) {
    int w = (blockIdx.x * blockDim.x + threadIdx.x) >> 5;
    int lane = threadIdx.x & 31;
    if (w >= NN) return;
    int beg = g_off[w], end = g_off[w + 1];
    const unsigned* P = (const unsigned*)g_p16;   // row = 32 half2
    float a0 = 0.f, a1 = 0.f, b0 = 0.f, b1 = 0.f;
    int e = beg;
    for (; e + 3 < end; e += 4) {
        int s0 = g_csrc[e], s1 = g_csrc[e + 1], s2 = g_csrc[e + 2], s3 = g_csrc[e + 3];
        unsigned u0 = __ldg(&P[(size_t)s0 * 32 + lane]);
        unsigned u1 = __ldg(&P[(size_t)s1 * 32 + lane]);
        unsigned u2 = __ldg(&P[(size_t)s2 * 32 + lane]);
        unsigned u3 = __ldg(&P[(size_t)s3 * 32 + lane]);
        float2 f;
        f = __half22float2(*(__half2*)&u0); a0 += f.x; a1 += f.y;
        f = __half22float2(*(__half2*)&u1); b0 += f.x; b1 += f.y;
        f = __half22float2(*(__half2*)&u2); a0 += f.x; a1 += f.y;
        f = __half22float2(*(__half2*)&u3); b0 += f.x; b1 += f.y;
    }
    for (; e < end; e++) {
        unsigned u = __ldg(&P[(size_t)g_csrc[e] * 32 + lane]);
        float2 f = __half22float2(*(__half2*)&u);
        a0 += f.x; a1 += f.y;
    }
    float inv = g_invdeg[w];
    float2 q = ((const float2*)g_q)[(size_t)w * 32 + lane];
    float2 bb = ((const float2*)b2)[lane];
    float2 o = make_float2((a0 + b0) * inv + q.x + bb.x,
                           (a1 + b1) * inv + q.y + bb.y);
    ((float2*)out)[(size_t)w * 32 + lane] = o;
}

// ---------------------------------------------------------------------------
// weight pre-transpose + fp16 conversion
// ---------------------------------------------------------------------------
__global__ void wt1_kernel(const float* __restrict__ W1l, const float* __restrict__ W1r) {
    int i = blockIdx.x * blockDim.x + threadIdx.x;   // 32768
    int k = i >> 7, f = i & 127;
    float v = (k < 128) ? W1l[f * 128 + k] : W1r[f * 128 + (k - 128)];
    g_wt1h[k * 128 + f] = __float2half_rn(v);
}
__global__ void wt2_kernel(const float* __restrict__ W2l, const float* __restrict__ W2r) {
    int i = blockIdx.x * blockDim.x + threadIdx.x;   // 16384
    int k = i >> 7, f = i & 127;
    float v = (f < 64) ? W2l[f * 128 + k] : W2r[(f - 64) * 128 + k];
    g_wt2h[k * 128 + f] = __float2half_rn(v);
}

// ---------------------------------------------------------------------------
// GEMMs (fp16 wmma 16x16x16, fp32 accum, cp.async double-buffered).
// CTA: 128 nodes x 128 feats; 8 warps 4(m) x 2(n); warp tile 32x64.
// K chunk = 64 per buffer. A: 128x64 halfs (stride 72), W: 64x128 (stride 136).
// ---------------------------------------------------------------------------
#define ALDH 72
#define WLDH 136
#define CLD  136
#define BUFH (128 * ALDH + 64 * WLDH)        // 17920 halfs per buffer
#define SM_BYTES (2 * BUFH * 2 + 1024)       // buffers (union Cs) + BN tables

__global__ void __launch_bounds__(256, 2) gemm1_kernel(
    const float* __restrict__ b1, const float* __restrict__ gmm,
    const float* __restrict__ bet, const float* __restrict__ mean,
    const float* __restrict__ var)
{
    extern __shared__ __align__(16) char smraw[];
    __half* smh = (__half*)smraw;
    float* Cs = (float*)smraw;                      // union
    float* Ssc = (float*)(smraw + 2 * BUFH * 2);
    float* Ssh = Ssc + 128;

    const int tid = threadIdx.x;
    const int wid = tid >> 5;
    const int wm = wid >> 1;
    const int wn = wid & 1;
    const int n0 = blockIdx.x * 128;
    const unsigned smu = (unsigned)__cvta_generic_to_shared(smraw);

    if (tid < 128) {
        float s = rsqrtf(var[tid] + 1e-5f) * gmm[tid];
        Ssc[tid] = s;
        Ssh[tid] = (b1[tid] - mean[tid]) * s + bet[tid];
    }

    wmma::fragment<wmma::accumulator, 16, 16, 16, float> acc[2][4];
#pragma unroll
    for (int i = 0; i < 2; i++)
#pragma unroll
        for (int j = 0; j < 4; j++) wmma::fill_fragment(acc[i][j], 0.f);

    const __half* A16 = g_a16;
    const __half* X16 = g_x16;
    const __half* WT = g_wt1h;

    // kc in [0,4): k-window kc*64 of K=256 ([agg|x] concat)
    auto stage = [&](int kc, int bufi) {
        unsigned base = smu + (unsigned)(bufi * BUFH * 2);
#pragma unroll
        for (int it = 0; it < 4; it++) {
            int t = tid + it * 256;          // 1024 chunks of 8 halfs
            int row = t >> 3, q = t & 7;
            int gn = n0 + row;
            unsigned dst = base + (unsigned)((row * ALDH + q * 8) * 2);
            if (kc < 2) {
                CPA16(dst, A16 + (size_t)gn * HID + kc * 64 + q * 8);
            } else {
                int sz = (gn < NN) ? 16 : 0;
                CPA16Z(dst, X16 + (size_t)gn * HID + (kc - 2) * 64 + q * 8, sz);
            }
        }
#pragma unroll
        for (int it = 0; it < 4; it++) {
            int t = tid + it * 256;          // 1024 chunks: 64 k-rows x 16
            int kr = t >> 4, fq = t & 15;
            unsigned dst = base + (unsigned)((128 * ALDH + kr * WLDH + fq * 8) * 2);
            CPA16(dst, WT + (size_t)(kc * 64 + kr) * HID + fq * 8);
        }
    };

    stage(0, 0);
    CPA_COMMIT();

    for (int kc = 0; kc < 4; kc++) {
        int cur = kc & 1;
        if (kc < 3) stage(kc + 1, cur ^ 1);
        CPA_COMMIT();
        if (kc < 3) CPA_WAIT1(); else CPA_WAIT0();
        __syncthreads();

        __half* As = smh + cur * BUFH;
        __half* Ws = As + 128 * ALDH;
#pragma unroll
        for (int k16 = 0; k16 < 4; k16++) {
            wmma::fragment<wmma::matrix_a, 16, 16, 16, __half, wmma::row_major> a[2];
#pragma unroll
            for (int i = 0; i < 2; i++)
                wmma::load_matrix_sync(a[i], As + (wm * 32 + i * 16) * ALDH + k16 * 16, ALDH);
#pragma unroll
            for (int nf = 0; nf < 4; nf++) {
                wmma::fragment<wmma::matrix_b, 16, 16, 16, __half, wmma::row_major> b;
                wmma::load_matrix_sync(b, Ws + (k16 * 16) * WLDH + wn * 64 + nf * 16, WLDH);
#pragma unroll
                for (int i = 0; i < 2; i++)
                    wmma::mma_sync(acc[i][nf], a[i], b, acc[i][nf]);
            }
        }
        __syncthreads();
    }

    // epilogue: BN + ReLU -> h16
#pragma unroll
    for (int i = 0; i < 2; i++)
#pragma unroll
        for (int nf = 0; nf < 4; nf++)
            wmma::store_matrix_sync(Cs + (wm * 32 + i * 16) * CLD + wn * 64 + nf * 16,
                                    acc[i][nf], CLD, wmma::mem_row_major);
    __syncthreads();
    {
        int row = tid >> 1, half = tid & 1;
        int gn = n0 + row;
        uint2* dst = (uint2*)(g_h16 + (size_t)gn * HID + half * 64);
        const float* src = Cs + row * CLD + half * 64;
#pragma unroll
        for (int j = 0; j < 16; j++) {
            float4 v = *(const float4*)(src + j * 4);
            int f = half * 64 + j * 4;
            float o0 = fmaxf(v.x * Ssc[f + 0] + Ssh[f + 0], 0.f);
            float o1 = fmaxf(v.y * Ssc[f + 1] + Ssh[f + 1], 0.f);
            float o2 = fmaxf(v.z * Ssc[f + 2] + Ssh[f + 2], 0.f);
            float o3 = fmaxf(v.w * Ssc[f + 3] + Ssh[f + 3], 0.f);
            __half2 h0 = __floats2half2_rn(o0, o1);
            __half2 h1 = __floats2half2_rn(o2, o3);
            uint2 u;
            u.x = *(unsigned*)&h0;
            u.y = *(unsigned*)&h1;
            dst[j] = u;
        }
    }
}

// ---------------------------------------------------------------------------
// Layer-2 fused GEMM: [p | q] = h16 @ Wt2.  p -> fp16, q -> fp32.
// ---------------------------------------------------------------------------
__global__ void __launch_bounds__(256, 2) gemm2_kernel()
{
    extern __shared__ __align__(16) char smraw[];
    __half* smh = (__half*)smraw;
    float* Cs = (float*)smraw;

    const int tid = threadIdx.x;
    const int wid = tid >> 5;
    const int wm = wid >> 1;
    const int wn = wid & 1;
    const int n0 = blockIdx.x * 128;
    const unsigned smu = (unsigned)__cvta_generic_to_shared(smraw);

    wmma::fragment<wmma::accumulator, 16, 16, 16, float> acc[2][4];
#pragma unroll
    for (int i = 0; i < 2; i++)
#pragma unroll
        for (int j = 0; j < 4; j++) wmma::fill_fragment(acc[i][j], 0.f);

    const __half* H16 = g_h16;
    const __half* WT = g_wt2h;

    auto stage = [&](int kc, int bufi) {
        unsigned base = smu + (unsigned)(bufi * BUFH * 2);
#pragma unroll
        for (int it = 0; it < 4; it++) {
            int t = tid + it * 256;
            int row = t >> 3, q = t & 7;
            unsigned dst = base + (unsigned)((row * ALDH + q * 8) * 2);
            CPA16(dst, H16 + (size_t)(n0 + row) * HID + kc * 64 + q * 8);
        }
#pragma unroll
        for (int it = 0; it < 4; it++) {
            int t = tid + it * 256;
            int kr = t >> 4, fq = t & 15;
            unsigned dst = base + (unsigned)((128 * ALDH + kr * WLDH + fq * 8) * 2);
            CPA16(dst, WT + (size_t)(kc * 64 + kr) * HID + fq * 8);
        }
    };

    stage(0, 0);
    CPA_COMMIT();

    for (int kc = 0; kc < 2; kc++) {
        int cur = kc & 1;
        if (kc < 1) stage(kc + 1, cur ^ 1);
        CPA_COMMIT();
        if (kc < 1) CPA_WAIT1(); else CPA_WAIT0();
        __syncthreads();

        __half* As = smh + cur * BUFH;
        __half* Ws = As + 128 * ALDH;
#pragma unroll
        for (int k16 = 0; k16 < 4; k16++) {
            wmma::fragment<wmma::matrix_a, 16, 16, 16, __half, wmma::row_major> a[2];
#pragma unroll
            for (int i = 0; i < 2; i++)
                wmma::load_matrix_sync(a[i], As + (wm * 32 + i * 16) * ALDH + k16 * 16, ALDH);
#pragma unroll
            for (int nf = 0; nf < 4; nf++) {
                wmma::fragment<wmma::matrix_b, 16, 16, 16, __half, wmma::row_major> b;
                wmma::load_matrix_sync(b, Ws + (k16 * 16) * WLDH + wn * 64 + nf * 16, WLDH);
#pragma unroll
                for (int i = 0; i < 2; i++)
                    wmma::mma_sync(acc[i][nf], a[i], b, acc[i][nf]);
            }
        }
        __syncthreads();
    }

    // epilogue: p cols [0,64) -> fp16, q cols [64,128) -> fp32
#pragma unroll
    for (int i = 0; i < 2; i++)
#pragma unroll
        for (int nf = 0; nf < 4; nf++)
            wmma::store_matrix_sync(Cs + (wm * 32 + i * 16) * CLD + wn * 64 + nf * 16,
                                    acc[i][nf], CLD, wmma::mem_row_major);
    __syncthreads();
    {
        int row = tid >> 1, half = tid & 1;
        int gn = n0 + row;
        const float* src = Cs + row * CLD + half * 64;
        if (half == 0) {
            uint2* dst = (uint2*)(g_p16 + (size_t)gn * OF);
#pragma unroll
            for (int j = 0; j < 16; j++) {
                float4 v = *(const float4*)(src + j * 4);
                __half2 h0 = __floats2half2_rn(v.x, v.y);
                __half2 h1 = __floats2half2_rn(v.z, v.w);
                uint2 u;
                u.x = *(unsigned*)&h0;
                u.y = *(unsigned*)&h1;
                dst[j] = u;
            }
        } else {
            float4* dst = (float4*)(g_q + (size_t)gn * OF);
#pragma unroll
            for (int j = 0; j < 16; j++)
                dst[j] = *(const float4*)(src + j * 4);
        }
    }
}

// ---------------------------------------------------------------------------
// Launch
// ---------------------------------------------------------------------------
extern "C" void kernel_launch(void* const* d_in, const int* in_sizes, int n_in,
                              void* d_out, int out_size) {
    const float* x    = (const float*)d_in[0];
    const void*  ei   = d_in[1];
    const float* W1l  = (const float*)d_in[2];
    const float* b1   = (const float*)d_in[3];
    const float* W1r  = (const float*)d_in[4];
    const float* gmm  = (const float*)d_in[5];
    const float* bet  = (const float*)d_in[6];
    const float* mean = (const float*)d_in[7];
    const float* var  = (const float*)d_in[8];
    const float* W2l  = (const float*)d_in[9];
    const float* b2   = (const float*)d_in[10];
    const float* W2r  = (const float*)d_in[11];
    float* out = (float*)d_out;

    cudaFuncSetAttribute(gemm1_kernel, cudaFuncAttributeMaxDynamicSharedMemorySize, SM_BYTES);
    cudaFuncSetAttribute(gemm2_kernel, cudaFuncAttributeMaxDynamicSharedMemorySize, SM_BYTES);

    void* degp = 0;
    cudaGetSymbolAddress(&degp, g_deg);

    detect_kernel<<<1, 256>>>((const int*)ei);
    cudaMemsetAsync(degp, 0, sizeof(int) * NNP, 0);
    wt1_kernel<<<128, 256>>>(W1l, W1r);
    wt2_kernel<<<64, 256>>>(W2l, W2r);
    x16_kernel<<<(NN * 32 + 255) / 256, 256>>>(x);

    deg_kernel<<<(NE + 255) / 256, 256>>>(ei);
    scan1_kernel<<<NNP / 128, 128>>>();
    scan2_kernel<<<1, 1024>>>(NNP / 128);
    scan3_kernel<<<NNP / 128, 128>>>();
    sort_kernel<<<(NE + 255) / 256, 256>>>(ei);

    agg1_kernel<<<NNP / 8, 256>>>();

    const int NB = NNP / 128;  // 782
    gemm1_kernel<<<NB, 256, SM_BYTES>>>(b1, gmm, bet, mean, var);
    gemm2_kernel<<<NB, 256, SM_BYTES>>>();
    agg2_final_kernel<<<NN / 8, 256>>>(b2, out);
}

// round 7
// speedup vs baseline: 3.0355x; 1.0756x over previous
#include <cuda_runtime.h>
#include <cuda_fp16.h>
#include <mma.h>
using namespace nvcuda;

#define NN 100000
#define NNP 100096           // 782*128
#define NE 1600000
#define HID 128
#define OF 64

// ---------------- scratch (device globals; no allocation allowed) ----------
__device__ __half g_x16[NN * HID];    // fp16 copy of x (gather + GEMM source)
__device__ __half g_a16[NNP * HID];   // mean aggregation of x, fp16
__device__ __half g_p16[NNP * OF];    // h @ W2_l.T, fp16 (gather source)
__device__ float  g_q[NNP * OF];      // h @ W2_r.T, fp32
__device__ __half g_wt1h[256 * HID];  // [W1l;W1r] transposed [k][f], fp16
__device__ __half g_wt2h[HID * HID];  // [W2l|W2r] transposed [k][f], fp16
__device__ int    g_deg[NNP];
__device__ float  g_invdeg[NNP];
__device__ int    g_off[NNP + 1];     // CSR offsets (by dst)
__device__ int    g_cur[NNP];         // counting-sort cursors
__device__ int    g_csrc[NE];         // src sorted by dst
__device__ int    g_tmp[NNP];
__device__ int    g_bsum[1024];
__device__ int    g_boff[1024];
__device__ int    g_is64;

#define CPA16(dst, src) \
    asm volatile("cp.async.cg.shared.global [%0], [%1], 16;" :: "r"(dst), "l"(src))
#define CPA16Z(dst, src, sz) \
    asm volatile("cp.async.cg.shared.global [%0], [%1], 16, %2;" :: "r"(dst), "l"(src), "r"(sz))
#define CPA_COMMIT() asm volatile("cp.async.commit_group;")
#define CPA_WAIT1()  asm volatile("cp.async.wait_group 1;")
#define CPA_WAIT0()  asm volatile("cp.async.wait_group 0;")

// ---------------------------------------------------------------------------
// dtype detection: int64 edge_index <=> hi words of first 256 entries all 0
// ---------------------------------------------------------------------------
__global__ void detect_kernel(const int* ei32) {
    __shared__ int cnt;
    if (threadIdx.x == 0) cnt = 0;
    __syncthreads();
    if (ei32[2 * threadIdx.x + 1] != 0) atomicAdd(&cnt, 1);
    __syncthreads();
    if (threadIdx.x == 0) g_is64 = (cnt == 0) ? 1 : 0;
}

__device__ __forceinline__ int ld_edge(const void* ei, long long idx, int is64) {
    return is64 ? (int)((const long long*)ei)[idx] : ((const int*)ei)[idx];
}

// ---------------------------------------------------------------------------
// Fused independent preprocessing (concurrent via block ranges):
//   [0,12500)      x -> fp16
//   [12500,18750)  degree count
//   [18750,18878)  wt1 transpose+fp16
//   [18878,18942)  wt2 transpose+fp16
// ---------------------------------------------------------------------------
#define PRE_X   12500
#define PRE_DEG 18750
#define PRE_W1  18878
#define PRE_GRID 18942

__global__ void pre_kernel(const float* __restrict__ x, const void* ei,
                           const float* __restrict__ W1l, const float* __restrict__ W1r,
                           const float* __restrict__ W2l, const float* __restrict__ W2r) {
    int b = blockIdx.x;
    int tid = threadIdx.x;
    if (b < PRE_X) {
        int i = b * 256 + tid;                    // < NN*32
        float4 v = ((const float4*)x)[i];
        __half2 h0 = __floats2half2_rn(v.x, v.y);
        __half2 h1 = __floats2half2_rn(v.z, v.w);
        uint2 u;
        u.x = *(unsigned*)&h0;
        u.y = *(unsigned*)&h1;
        ((uint2*)g_x16)[i] = u;
    } else if (b < PRE_DEG) {
        int e = (b - PRE_X) * 256 + tid;          // < NE
        int dst = ld_edge(ei, (long long)NE + e, g_is64);
        atomicAdd(&g_deg[dst], 1);
    } else if (b < PRE_W1) {
        int i = (b - PRE_DEG) * 256 + tid;        // < 32768
        int k = i >> 7, f = i & 127;
        float v = (k < 128) ? W1l[f * 128 + k] : W1r[f * 128 + (k - 128)];
        g_wt1h[k * 128 + f] = __float2half_rn(v);
    } else {
        int i = (b - PRE_W1) * 256 + tid;         // < 16384
        int k = i >> 7, f = i & 127;
        float v = (f < 64) ? W2l[f * 128 + k] : W2r[(f - 64) * 128 + k];
        g_wt2h[k * 128 + f] = __float2half_rn(v);
    }
}

// ---------------------------------------------------------------------------
// 3-phase exclusive scan of degrees -> g_off (+cursors +invdeg fused)
// ---------------------------------------------------------------------------
__global__ void scan1_kernel() {
    __shared__ int s[128];
    int i = blockIdx.x * 128 + threadIdx.x;
    int t = threadIdx.x;
    s[t] = g_deg[i];
    __syncthreads();
    for (int o = 1; o < 128; o <<= 1) {
        int v = (t >= o) ? s[t - o] : 0;
        __syncthreads();
        s[t] += v;
        __syncthreads();
    }
    g_tmp[i] = s[t];
    if (t == 127) g_bsum[blockIdx.x] = s[127];
}
__global__ void scan2_kernel(int nb) {
    __shared__ int s[1024];
    int t = threadIdx.x;
    int own = (t < nb) ? g_bsum[t] : 0;
    s[t] = own;
    __syncthreads();
    for (int o = 1; o < 1024; o <<= 1) {
        int v = (t >= o) ? s[t - o] : 0;
        __syncthreads();
        s[t] += v;
        __syncthreads();
    }
    if (t < nb) g_boff[t] = s[t] - own;   // exclusive
}
__global__ void scan3_kernel() {
    int i = blockIdx.x * 128 + threadIdx.x;
    int d = g_deg[i];
    int incl = g_tmp[i] + g_boff[blockIdx.x];
    g_off[i + 1] = incl;
    g_cur[i] = incl - d;
    g_invdeg[i] = 1.0f / fmaxf((float)d, 1.0f);
    if (i == 0) g_off[0] = 0;
}

// ---------------------------------------------------------------------------
// counting sort: csrc sorted by dst
// ---------------------------------------------------------------------------
__global__ void sort_kernel(const void* ei) {
    int e = blockIdx.x * blockDim.x + threadIdx.x;
    if (e < NE) {
        int is64 = g_is64;
        int src = ld_edge(ei, e, is64);
        int dst = ld_edge(ei, (long long)NE + e, is64);
        int pos = atomicAdd(&g_cur[dst], 1);
        g_csrc[pos] = src;
    }
}

// ---------------------------------------------------------------------------
// CSR mean-aggregate x16 -> g_a16 (fp16, fp32 accum). Warp per node.
// 8-edge unroll for MLP.
// ---------------------------------------------------------------------------
__global__ void agg1_kernel() {
    int w = (blockIdx.x * blockDim.x + threadIdx.x) >> 5;
    int lane = threadIdx.x & 31;
    if (w >= NNP) return;
    int beg = g_off[w], end = g_off[w + 1];
    const uint2* X = (const uint2*)g_x16;   // row = 32 uint2
    float a0 = 0.f, a1 = 0.f, a2 = 0.f, a3 = 0.f;
    float b0 = 0.f, b1 = 0.f, b2 = 0.f, b3 = 0.f;
    int e = beg;
    for (; e + 7 < end; e += 8) {
        uint2 u[8];
#pragma unroll
        for (int j = 0; j < 8; j++)
            u[j] = __ldg(&X[(size_t)g_csrc[e + j] * 32 + lane]);
#pragma unroll
        for (int j = 0; j < 8; j += 2) {
            float2 f;
            f = __half22float2(*(__half2*)&u[j].x);     a0 += f.x; a1 += f.y;
            f = __half22float2(*(__half2*)&u[j].y);     a2 += f.x; a3 += f.y;
            f = __half22float2(*(__half2*)&u[j + 1].x); b0 += f.x; b1 += f.y;
            f = __half22float2(*(__half2*)&u[j + 1].y); b2 += f.x; b3 += f.y;
        }
    }
    for (; e + 3 < end; e += 4) {
        uint2 u[4];
#pragma unroll
        for (int j = 0; j < 4; j++)
            u[j] = __ldg(&X[(size_t)g_csrc[e + j] * 32 + lane]);
#pragma unroll
        for (int j = 0; j < 4; j += 2) {
            float2 f;
            f = __half22float2(*(__half2*)&u[j].x);     a0 += f.x; a1 += f.y;
            f = __half22float2(*(__half2*)&u[j].y);     a2 += f.x; a3 += f.y;
            f = __half22float2(*(__half2*)&u[j + 1].x); b0 += f.x; b1 += f.y;
            f = __half22float2(*(__half2*)&u[j + 1].y); b2 += f.x; b3 += f.y;
        }
    }
    for (; e < end; e++) {
        uint2 u = __ldg(&X[(size_t)g_csrc[e] * 32 + lane]);
        float2 f;
        f = __half22float2(*(__half2*)&u.x); a0 += f.x; a1 += f.y;
        f = __half22float2(*(__half2*)&u.y); a2 += f.x; a3 += f.y;
    }
    float inv = g_invdeg[w];
    __half2 h0 = __floats2half2_rn((a0 + b0) * inv, (a1 + b1) * inv);
    __half2 h1 = __floats2half2_rn((a2 + b2) * inv, (a3 + b3) * inv);
    uint2 o;
    o.x = *(unsigned*)&h0;
    o.y = *(unsigned*)&h1;
    ((uint2*)g_a16)[(size_t)w * 32 + lane] = o;
}

// ---------------------------------------------------------------------------
// CSR mean-aggregate p16 + q + b2 -> out. Warp per node.
// ---------------------------------------------------------------------------
__global__ void agg2_final_kernel(const float* __restrict__ b2,
                                  float* __restrict__ out) {
    int w = (blockIdx.x * blockDim.x + threadIdx.x) >> 5;
    int lane = threadIdx.x & 31;
    if (w >= NN) return;
    int beg = g_off[w], end = g_off[w + 1];
    const unsigned* P = (const unsigned*)g_p16;   // row = 32 half2
    float a0 = 0.f, a1 = 0.f, b0 = 0.f, b1 = 0.f;
    int e = beg;
    for (; e + 7 < end; e += 8) {
        unsigned u[8];
#pragma unroll
        for (int j = 0; j < 8; j++)
            u[j] = __ldg(&P[(size_t)g_csrc[e + j] * 32 + lane]);
#pragma unroll
        for (int j = 0; j < 8; j += 2) {
            float2 f;
            f = __half22float2(*(__half2*)&u[j]);     a0 += f.x; a1 += f.y;
            f = __half22float2(*(__half2*)&u[j + 1]); b0 += f.x; b1 += f.y;
        }
    }
    for (; e + 3 < end; e += 4) {
        unsigned u[4];
#pragma unroll
        for (int j = 0; j < 4; j++)
            u[j] = __ldg(&P[(size_t)g_csrc[e + j] * 32 + lane]);
#pragma unroll
        for (int j = 0; j < 4; j += 2) {
            float2 f;
            f = __half22float2(*(__half2*)&u[j]);     a0 += f.x; a1 += f.y;
            f = __half22float2(*(__half2*)&u[j + 1]); b0 += f.x; b1 += f.y;
        }
    }
    for (; e < end; e++) {
        unsigned u = __ldg(&P[(size_t)g_csrc[e] * 32 + lane]);
        float2 f = __half22float2(*(__half2*)&u);
        a0 += f.x; a1 += f.y;
    }
    float inv = g_invdeg[w];
    float2 q = ((const float2*)g_q)[(size_t)w * 32 + lane];
    float2 bb = ((const float2*)b2)[lane];
    float2 o = make_float2((a0 + b0) * inv + q.x + bb.x,
                           (a1 + b1) * inv + q.y + bb.y);
    ((float2*)out)[(size_t)w * 32 + lane] = o;
}

// ---------------------------------------------------------------------------
// Fused layer-1 + layer-2 GEMM (fp16 wmma, fp32 accum):
//   h  = relu(BN( [a16 | x16] @ Wt1 + b1 ))   (h lives in smem only)
//   [p16 | q] = h @ Wt2
// CTA: 128 nodes; 8 warps 4(m) x 2(n); warp tile 32x64.
// smem: 2 ping-pong buffers (union: Cs float 128x136) + Hs + Wt2s + BN.
// ---------------------------------------------------------------------------
#define ALDH 72
#define WLDH 136
#define CLD  136
#define BUFH (128 * ALDH + 64 * WLDH)        // 17920 halfs per buffer
#define HS_OFF   (2 * BUFH)                  // 35840 halfs
#define WT2_OFF  (HS_OFF + 128 * WLDH)       // +17408
#define BN_BYTE  ((WT2_OFF + 128 * WLDH) * 2)
#define SM_BYTES (BN_BYTE + 1024)

__global__ void __launch_bounds__(256, 1) gemm12_kernel(
    const float* __restrict__ b1, const float* __restrict__ gmm,
    const float* __restrict__ bet, const float* __restrict__ mean,
    const float* __restrict__ var)
{
    extern __shared__ __align__(16) char smraw[];
    __half* smh = (__half*)smraw;
    float* Cs = (float*)smraw;                 // union with ping-pong buffers
    __half* Hs = smh + HS_OFF;
    __half* W2s = smh + WT2_OFF;
    float* Ssc = (float*)(smraw + BN_BYTE);
    float* Ssh = Ssc + 128;

    const int tid = threadIdx.x;
    const int wid = tid >> 5;
    const int wm = wid >> 1;
    const int wn = wid & 1;
    const int n0 = blockIdx.x * 128;
    const unsigned smu = (unsigned)__cvta_generic_to_shared(smraw);

    if (tid < 128) {
        float s = rsqrtf(var[tid] + 1e-5f) * gmm[tid];
        Ssc[tid] = s;
        Ssh[tid] = (b1[tid] - mean[tid]) * s + bet[tid];
    }

    wmma::fragment<wmma::accumulator, 16, 16, 16, float> acc[2][4];
#pragma unroll
    for (int i = 0; i < 2; i++)
#pragma unroll
        for (int j = 0; j < 4; j++) wmma::fill_fragment(acc[i][j], 0.f);

    const __half* A16 = g_a16;
    const __half* X16 = g_x16;
    const __half* WT = g_wt1h;

    auto stage = [&](int kc, int bufi) {
        unsigned base = smu + (unsigned)(bufi * BUFH * 2);
#pragma unroll
        for (int it = 0; it < 4; it++) {
            int t = tid + it * 256;          // 1024 chunks of 8 halfs
            int row = t >> 3, q = t & 7;
            int gn = n0 + row;
            unsigned dst = base + (unsigned)((row * ALDH + q * 8) * 2);
            if (kc < 2) {
                CPA16(dst, A16 + (size_t)gn * HID + kc * 64 + q * 8);
            } else {
                int sz = (gn < NN) ? 16 : 0;
                CPA16Z(dst, X16 + (size_t)gn * HID + (kc - 2) * 64 + q * 8, sz);
            }
        }
#pragma unroll
        for (int it = 0; it < 4; it++) {
            int t = tid + it * 256;          // 1024 chunks: 64 k-rows x 16
            int kr = t >> 4, fq = t & 15;
            unsigned dst = base + (unsigned)((128 * ALDH + kr * WLDH + fq * 8) * 2);
            CPA16(dst, WT + (size_t)(kc * 64 + kr) * HID + fq * 8);
        }
    };

    // prefetch Wt2 (128x128) into W2s as part of the first commit group
#pragma unroll
    for (int it = 0; it < 8; it++) {
        int t = tid + it * 256;              // 2048 chunks
        int kr = t >> 4, fq = t & 15;
        unsigned dst = smu + (unsigned)((WT2_OFF + kr * WLDH + fq * 8) * 2);
        CPA16(dst, g_wt2h + (size_t)kr * HID + fq * 8);
    }
    stage(0, 0);
    CPA_COMMIT();

    // ---- layer 1: K = 256 in 4 chunks of 64 ----
    for (int kc = 0; kc < 4; kc++) {
        int cur = kc & 1;
        if (kc < 3) stage(kc + 1, cur ^ 1);
        CPA_COMMIT();
        if (kc < 3) CPA_WAIT1(); else CPA_WAIT0();
        __syncthreads();

        __half* As = smh + cur * BUFH;
        __half* Ws = As + 128 * ALDH;
#pragma unroll
        for (int k16 = 0; k16 < 4; k16++) {
            wmma::fragment<wmma::matrix_a, 16, 16, 16, __half, wmma::row_major> a[2];
#pragma unroll
            for (int i = 0; i < 2; i++)
                wmma::load_matrix_sync(a[i], As + (wm * 32 + i * 16) * ALDH + k16 * 16, ALDH);
#pragma unroll
            for (int nf = 0; nf < 4; nf++) {
                wmma::fragment<wmma::matrix_b, 16, 16, 16, __half, wmma::row_major> b;
                wmma::load_matrix_sync(b, Ws + (k16 * 16) * WLDH + wn * 64 + nf * 16, WLDH);
#pragma unroll
                for (int i = 0; i < 2; i++)
                    wmma::mma_sync(acc[i][nf], a[i], b, acc[i][nf]);
            }
        }
        __syncthreads();
    }

    // ---- layer-1 epilogue: acc -> Cs -> BN+ReLU -> Hs (fp16, smem only) ----
#pragma unroll
    for (int i = 0; i < 2; i++)
#pragma unroll
        for (int nf = 0; nf < 4; nf++)
            wmma::store_matrix_sync(Cs + (wm * 32 + i * 16) * CLD + wn * 64 + nf * 16,
                                    acc[i][nf], CLD, wmma::mem_row_major);
    __syncthreads();
    {
        int row = tid >> 1, half = tid & 1;
        const float* src = Cs + row * CLD + half * 64;
        __half2* dst = (__half2*)(Hs + row * WLDH + half * 64);
#pragma unroll
        for (int j = 0; j < 16; j++) {
            float4 v = *(const float4*)(src + j * 4);
            int f = half * 64 + j * 4;
            float o0 = fmaxf(v.x * Ssc[f + 0] + Ssh[f + 0], 0.f);
            float o1 = fmaxf(v.y * Ssc[f + 1] + Ssh[f + 1], 0.f);
            float o2 = fmaxf(v.z * Ssc[f + 2] + Ssh[f + 2], 0.f);
            float o3 = fmaxf(v.w * Ssc[f + 3] + Ssh[f + 3], 0.f);
            dst[j * 2 + 0] = __floats2half2_rn(o0, o1);
            dst[j * 2 + 1] = __floats2half2_rn(o2, o3);
        }
    }
    __syncthreads();

    // ---- layer 2: [p|q] = Hs @ W2s (all operands in smem) ----
#pragma unroll
    for (int i = 0; i < 2; i++)
#pragma unroll
        for (int j = 0; j < 4; j++) wmma::fill_fragment(acc[i][j], 0.f);
#pragma unroll
    for (int k16 = 0; k16 < 8; k16++) {
        wmma::fragment<wmma::matrix_a, 16, 16, 16, __half, wmma::row_major> a[2];
#pragma unroll
        for (int i = 0; i < 2; i++)
            wmma::load_matrix_sync(a[i], Hs + (wm * 32 + i * 16) * WLDH + k16 * 16, WLDH);
#pragma unroll
        for (int nf = 0; nf < 4; nf++) {
            wmma::fragment<wmma::matrix_b, 16, 16, 16, __half, wmma::row_major> b;
            wmma::load_matrix_sync(b, W2s + (k16 * 16) * WLDH + wn * 64 + nf * 16, WLDH);
#pragma unroll
            for (int i = 0; i < 2; i++)
                wmma::mma_sync(acc[i][nf], a[i], b, acc[i][nf]);
        }
    }

    // ---- layer-2 epilogue: p cols [0,64) -> fp16, q cols [64,128) -> fp32 ----
#pragma unroll
    for (int i = 0; i < 2; i++)
#pragma unroll
        for (int nf = 0; nf < 4; nf++)
            wmma::store_matrix_sync(Cs + (wm * 32 + i * 16) * CLD + wn * 64 + nf * 16,
                                    acc[i][nf], CLD, wmma::mem_row_major);
    __syncthreads();
    {
        int row = tid >> 1, half = tid & 1;
        int gn = n0 + row;
        const float* src = Cs + row * CLD + half * 64;
        if (half == 0) {
            uint2* dst = (uint2*)(g_p16 + (size_t)gn * OF);
#pragma unroll
            for (int j = 0; j < 16; j++) {
                float4 v = *(const float4*)(src + j * 4);
                __half2 h0 = __floats2half2_rn(v.x, v.y);
                __half2 h1 = __floats2half2_rn(v.z, v.w);
                uint2 u;
                u.x = *(unsigned*)&h0;
                u.y = *(unsigned*)&h1;
                dst[j] = u;
            }
        } else {
            float4* dst = (float4*)(g_q + (size_t)gn * OF);
#pragma unroll
            for (int j = 0; j < 16; j++)
                dst[j] = *(const float4*)(src + j * 4);
        }
    }
}

// ---------------------------------------------------------------------------
// Launch
// ---------------------------------------------------------------------------
extern "C" void kernel_launch(void* const* d_in, const int* in_sizes, int n_in,
                              void* d_out, int out_size) {
    const float* x    = (const float*)d_in[0];
    const void*  ei   = d_in[1];
    const float* W1l  = (const float*)d_in[2];
    const float* b1   = (const float*)d_in[3];
    const float* W1r  = (const float*)d_in[4];
    const float* gmm  = (const float*)d_in[5];
    const float* bet  = (const float*)d_in[6];
    const float* mean = (const float*)d_in[7];
    const float* var  = (const float*)d_in[8];
    const float* W2l  = (const float*)d_in[9];
    const float* b2   = (const float*)d_in[10];
    const float* W2r  = (const float*)d_in[11];
    float* out = (float*)d_out;

    cudaFuncSetAttribute(gemm12_kernel, cudaFuncAttributeMaxDynamicSharedMemorySize, SM_BYTES);

    void* degp = 0;
    cudaGetSymbolAddress(&degp, g_deg);

    detect_kernel<<<1, 256>>>((const int*)ei);
    cudaMemsetAsync(degp, 0, sizeof(int) * NNP, 0);
    pre_kernel<<<PRE_GRID, 256>>>(x, ei, W1l, W1r, W2l, W2r);

    scan1_kernel<<<NNP / 128, 128>>>();
    scan2_kernel<<<1, 1024>>>(NNP / 128);
    scan3_kernel<<<NNP / 128, 128>>>();
    sort_kernel<<<(NE + 255) / 256, 256>>>(ei);

    agg1_kernel<<<NNP / 8, 256>>>();

    gemm12_kernel<<<NNP / 128, 256, SM_BYTES>>>(b1, gmm, bet, mean, var);
    agg2_final_kernel<<<NN / 8, 256>>>(b2, out);
}